// round 2
// baseline (speedup 1.0000x reference)
#include <cuda_runtime.h>
#include <math.h>

// ---------------------------------------------------------------------------
// Problem constants
// ---------------------------------------------------------------------------
#define BB   8
#define NN_  512
#define MM   510
#define PP_  511
#define PI_F 3.14159265358979323846f

#define NNN   (NN_*NN_)
#define BNN   (BB*NNN)
#define MMM   (MM*MM)
#define BMM   (BB*MMM)
#define PPP   (PP_*PP_)
#define BPP   (BB*PPP)
#define B4PP  (BB*4*PPP)
#define PM_   (PP_*MM)     // 511*510
#define MP_   (MM*PP_)     // 510*511
#define BPM   (BB*PP_*MM)
#define BMP   (BB*MM*PP_)

// ---------------------------------------------------------------------------
// Static device scratch (allocation-free rule: __device__ globals)
// ---------------------------------------------------------------------------
__device__ float d_x0[BNN];
__device__ float d_x1[BNN];
__device__ float d_st[5*BMM];       // sw,se,sn,ss,sc planes
__device__ float d_r1[BMM];
__device__ float d_Sf [PM_];        // [u][j]   u<511, j<510 : sin(pi*(j+1)*(u-255)/511)
__device__ float d_SfT[MP_];        // [j][u]
__device__ float d_Cm [MP_];        // [n][u]   n<510 : cos(pi*(u-255)*n/511)
__device__ float d_Sm [MP_];        // [n][u]
__device__ float d_CmT[PM_];        // [u][n]
__device__ float d_SmT[PM_];        // [u][n]
__device__ float d_T1[BPM];         // forward stage-1 (511x510 per batch)
__device__ float d_zar[B4PP];       // conv ping buffer real  [B][4][511][511]
__device__ float d_zai[B4PP];       //                  imag
__device__ float d_zbr[B4PP];       // conv pong buffer real
__device__ float d_zbi[B4PP];       //                  imag
__device__ float d_Pm[BMP];         // inverse stage-1 P (510x511 per batch)
__device__ float d_Qm[BMP];         // inverse stage-1 Q
__device__ float d_R0[BMM];         // ReF for call 0 (510x510 per batch)
__device__ float d_R1[BMM];         // ReF for call 1
__device__ double d_part[2*1024];   // reduction partials

// ---------------------------------------------------------------------------
// Trig matrices (exact integer phase reduction mod 1022, then sinf/cosf)
// ---------------------------------------------------------------------------
__global__ void trig_init_k()
{
    int x = blockIdx.x*blockDim.x + threadIdx.x;
    int y = blockIdx.y*blockDim.y + threadIdx.y;
    if (x >= PP_ || y >= PP_) return;
    if (x < MM) {
        int t = (x+1) * (y-255);
        int m = t % 1022; if (m < 0) m += 1022;
        float v = sinf((float)m * (PI_F/511.0f));
        d_Sf [y*MM  + x] = v;
        d_SfT[x*PP_ + y] = v;
    }
    if (y < MM) {
        int t = y * (x - 255);
        int m = t % 1022; if (m < 0) m += 1022;
        float ang = (float)m * (PI_F/511.0f);
        float c = cosf(ang), s = sinf(ang);
        d_Cm [y*PP_ + x] = c;
        d_Sm [y*PP_ + x] = s;
        d_CmT[x*MM  + y] = c;
        d_SmT[x*MM  + y] = s;
    }
}

// ---------------------------------------------------------------------------
// Stencil coefficients
// ---------------------------------------------------------------------------
__global__ void stencil_k(const float* __restrict__ coef)
{
    int idx = blockIdx.x*blockDim.x + threadIdx.x;
    if (idx >= BMM) return;
    int i = idx % MM;
    int j = (idx / MM) % MM;
    int b = idx / MMM;
    const float* cb = coef + b*MMM;
    float a   = cb[j*MM + i];
    float aw  = cb[j*MM + (i>0    ? i-1 : 0   )];
    float ae  = cb[j*MM + (i<MM-1 ? i+1 : MM-1)];
    float an  = cb[(j<MM-1 ? j+1 : MM-1)*MM + i];
    float as_ = cb[(j>0    ? j-1 : 0   )*MM + i];
    float sw = -2.f*aw *a/(aw +a);
    float se = -2.f*ae *a/(ae +a);
    float sn = -2.f*an *a/(an +a);
    float ss = -2.f*as_*a/(as_+a);
    d_st[0*BMM+idx] = sw;
    d_st[1*BMM+idx] = se;
    d_st[2*BMM+idx] = sn;
    d_st[3*BMM+idx] = ss;
    d_st[4*BMM+idx] = -(sw+se+sn+ss);
}

// A(x) at interior point (y,x) in [1,511)
__device__ __forceinline__ float applyA(const float* __restrict__ xb, int b, int y, int x)
{
    int s = b*MMM + (y-1)*MM + (x-1);
    return d_st[3*BMM+s]*xb[(y-1)*NN_+x]
         + d_st[0*BMM+s]*xb[y*NN_+x-1]
         + d_st[4*BMM+s]*xb[y*NN_+x]
         + d_st[1*BMM+s]*xb[y*NN_+x+1]
         + d_st[2*BMM+s]*xb[(y+1)*NN_+x];
}

__global__ void fill0_k(float* __restrict__ p, int n)
{
    int idx = blockIdx.x*blockDim.x + threadIdx.x;
    if (idx < n) p[idx] = 0.f;
}

__global__ void jacobi_k(const float* __restrict__ f, const float* __restrict__ xin,
                         float* __restrict__ xout, float w)
{
    int idx = blockIdx.x*blockDim.x + threadIdx.x;
    if (idx >= BNN) return;
    int x = idx % NN_;
    int y = (idx / NN_) % NN_;
    int b = idx / NNN;
    const float* xb = xin + b*NNN;
    float Ax = 0.f;
    if (y >= 1 && y < NN_-1 && x >= 1 && x < NN_-1) Ax = applyA(xb, b, y, x);
    xout[idx] = xin[idx] + w*(f[idx] - Ax);
}

__global__ void resid_k(const float* __restrict__ f, const float* __restrict__ xin)
{
    int idx = blockIdx.x*blockDim.x + threadIdx.x;
    if (idx >= BMM) return;
    int i = idx % MM;
    int j = (idx / MM) % MM;
    int b = idx / MMM;
    int y = j+1, x = i+1;
    d_r1[idx] = f[b*NNN + y*NN_ + x] - applyA(xin + b*NNN, b, y, x);
}

// zero channel-0 imag planes of a 4-channel complex buffer
__global__ void zero_ch0_k(float* __restrict__ z)
{
    int idx = blockIdx.x*blockDim.x + threadIdx.x;
    if (idx >= BPP) return;
    int b = idx / PPP;
    int r = idx % PPP;
    z[b*4*PPP + r] = 0.f;
}

// ---------------------------------------------------------------------------
// Batched SGEMM: C[b] = alpha * A[b] @ B[b]  (stride 0 => shared operand)
// Row-major, ld == logical width. 64x64x16 tile, 256 threads, 4x4 microtile.
// ---------------------------------------------------------------------------
#define GBM 64
#define GBN 64
#define GBK 16

__global__ __launch_bounds__(256) void gemm_k(
    const float* __restrict__ A, int sAb,
    const float* __restrict__ Bm, int sBb,
    float* __restrict__ C, int sCb,
    int Mn, int Nn, int Kn, float alpha)
{
    const float* Ab = A  + (size_t)blockIdx.z * sAb;
    const float* Bb = Bm + (size_t)blockIdx.z * sBb;
    float*       Cb = C  + (size_t)blockIdx.z * sCb;
    __shared__ float As[GBK][GBM+1];
    __shared__ float Bs[GBK][GBN];
    int tid = threadIdx.x;
    int tm = (tid >> 4) * 4;
    int tn = (tid & 15) * 4;
    int row0 = blockIdx.y * GBM;
    int col0 = blockIdx.x * GBN;
    float acc[4][4] = {};
    for (int k0 = 0; k0 < Kn; k0 += GBK) {
        #pragma unroll
        for (int i = tid; i < GBM*GBK; i += 256) {
            int k = i & (GBK-1); int m = i >> 4;
            int gm = row0 + m, gk = k0 + k;
            As[k][m] = (gm < Mn && gk < Kn) ? Ab[gm*Kn + gk] : 0.f;
        }
        #pragma unroll
        for (int i = tid; i < GBK*GBN; i += 256) {
            int n = i & (GBN-1); int k = i >> 6;
            int gk = k0 + k, gn = col0 + n;
            Bs[k][n] = (gk < Kn && gn < Nn) ? Bb[gk*Nn + gn] : 0.f;
        }
        __syncthreads();
        #pragma unroll
        for (int k = 0; k < GBK; k++) {
            float av[4], bv[4];
            #pragma unroll
            for (int i = 0; i < 4; i++) av[i] = As[k][tm+i];
            #pragma unroll
            for (int j = 0; j < 4; j++) bv[j] = Bs[k][tn+j];
            #pragma unroll
            for (int i = 0; i < 4; i++)
                #pragma unroll
                for (int j = 0; j < 4; j++)
                    acc[i][j] += av[i]*bv[j];
        }
        __syncthreads();
    }
    #pragma unroll
    for (int i = 0; i < 4; i++) {
        int gm = row0 + tm + i; if (gm >= Mn) continue;
        #pragma unroll
        for (int j = 0; j < 4; j++) {
            int gn = col0 + tn + j; if (gn >= Nn) continue;
            Cb[gm*Nn + gn] = alpha*acc[i][j];
        }
    }
}

// Inverse stage 1: P = A1@X + A2@Y ; Q = A1@Y - A2@X   (A1,A2 shared)
__global__ __launch_bounds__(256) void gemm_dualL_k(
    const float* __restrict__ A1, const float* __restrict__ A2,
    const float* __restrict__ X, int sXb,
    const float* __restrict__ Y, int sYb,
    float* __restrict__ Po, int sPb,
    float* __restrict__ Qo, int sQb,
    int Mn, int Nn, int Kn)
{
    const float* Xb = X + (size_t)blockIdx.z * sXb;
    const float* Yb = Y + (size_t)blockIdx.z * sYb;
    float* Pb = Po + (size_t)blockIdx.z * sPb;
    float* Qb = Qo + (size_t)blockIdx.z * sQb;
    __shared__ float As1[GBK][GBM+1];
    __shared__ float As2[GBK][GBM+1];
    __shared__ float BsX[GBK][GBN];
    __shared__ float BsY[GBK][GBN];
    int tid = threadIdx.x;
    int tm = (tid >> 4) * 4;
    int tn = (tid & 15) * 4;
    int row0 = blockIdx.y * GBM;
    int col0 = blockIdx.x * GBN;
    float accP[4][4] = {};
    float accQ[4][4] = {};
    for (int k0 = 0; k0 < Kn; k0 += GBK) {
        #pragma unroll
        for (int i = tid; i < GBM*GBK; i += 256) {
            int k = i & (GBK-1); int m = i >> 4;
            int gm = row0 + m, gk = k0 + k;
            bool ok = (gm < Mn && gk < Kn);
            As1[k][m] = ok ? A1[gm*Kn + gk] : 0.f;
            As2[k][m] = ok ? A2[gm*Kn + gk] : 0.f;
        }
        #pragma unroll
        for (int i = tid; i < GBK*GBN; i += 256) {
            int n = i & (GBN-1); int k = i >> 6;
            int gk = k0 + k, gn = col0 + n;
            bool ok = (gk < Kn && gn < Nn);
            BsX[k][n] = ok ? Xb[gk*Nn + gn] : 0.f;
            BsY[k][n] = ok ? Yb[gk*Nn + gn] : 0.f;
        }
        __syncthreads();
        #pragma unroll
        for (int k = 0; k < GBK; k++) {
            float a1[4], a2[4], xv[4], yv[4];
            #pragma unroll
            for (int i = 0; i < 4; i++) { a1[i] = As1[k][tm+i]; a2[i] = As2[k][tm+i]; }
            #pragma unroll
            for (int j = 0; j < 4; j++) { xv[j] = BsX[k][tn+j]; yv[j] = BsY[k][tn+j]; }
            #pragma unroll
            for (int i = 0; i < 4; i++)
                #pragma unroll
                for (int j = 0; j < 4; j++) {
                    accP[i][j] += a1[i]*xv[j] + a2[i]*yv[j];
                    accQ[i][j] += a1[i]*yv[j] - a2[i]*xv[j];
                }
        }
        __syncthreads();
    }
    #pragma unroll
    for (int i = 0; i < 4; i++) {
        int gm = row0 + tm + i; if (gm >= Mn) continue;
        #pragma unroll
        for (int j = 0; j < 4; j++) {
            int gn = col0 + tn + j; if (gn >= Nn) continue;
            Pb[gm*Nn + gn] = accP[i][j];
            Qb[gm*Nn + gn] = accQ[i][j];
        }
    }
}

// Inverse stage 2: R = X@B1 + Y@B2   (B1,B2 shared)
__global__ __launch_bounds__(256) void gemm_dualR_k(
    const float* __restrict__ X, int sXb,
    const float* __restrict__ Y, int sYb,
    const float* __restrict__ B1, const float* __restrict__ B2,
    float* __restrict__ Ro, int sRb,
    int Mn, int Nn, int Kn)
{
    const float* Xb = X + (size_t)blockIdx.z * sXb;
    const float* Yb = Y + (size_t)blockIdx.z * sYb;
    float* Rb = Ro + (size_t)blockIdx.z * sRb;
    __shared__ float AsX[GBK][GBM+1];
    __shared__ float AsY[GBK][GBM+1];
    __shared__ float Bs1[GBK][GBN];
    __shared__ float Bs2[GBK][GBN];
    int tid = threadIdx.x;
    int tm = (tid >> 4) * 4;
    int tn = (tid & 15) * 4;
    int row0 = blockIdx.y * GBM;
    int col0 = blockIdx.x * GBN;
    float acc[4][4] = {};
    for (int k0 = 0; k0 < Kn; k0 += GBK) {
        #pragma unroll
        for (int i = tid; i < GBM*GBK; i += 256) {
            int k = i & (GBK-1); int m = i >> 4;
            int gm = row0 + m, gk = k0 + k;
            bool ok = (gm < Mn && gk < Kn);
            AsX[k][m] = ok ? Xb[gm*Kn + gk] : 0.f;
            AsY[k][m] = ok ? Yb[gm*Kn + gk] : 0.f;
        }
        #pragma unroll
        for (int i = tid; i < GBK*GBN; i += 256) {
            int n = i & (GBN-1); int k = i >> 6;
            int gk = k0 + k, gn = col0 + n;
            bool ok = (gk < Kn && gn < Nn);
            Bs1[k][n] = ok ? B1[gk*Nn + gn] : 0.f;
            Bs2[k][n] = ok ? B2[gk*Nn + gn] : 0.f;
        }
        __syncthreads();
        #pragma unroll
        for (int k = 0; k < GBK; k++) {
            float ax[4], ay[4], b1[4], b2[4];
            #pragma unroll
            for (int i = 0; i < 4; i++) { ax[i] = AsX[k][tm+i]; ay[i] = AsY[k][tm+i]; }
            #pragma unroll
            for (int j = 0; j < 4; j++) { b1[j] = Bs1[k][tn+j]; b2[j] = Bs2[k][tn+j]; }
            #pragma unroll
            for (int i = 0; i < 4; i++)
                #pragma unroll
                for (int j = 0; j < 4; j++)
                    acc[i][j] += ax[i]*b1[j] + ay[i]*b2[j];
        }
        __syncthreads();
    }
    #pragma unroll
    for (int i = 0; i < 4; i++) {
        int gm = row0 + tm + i; if (gm >= Mn) continue;
        #pragma unroll
        for (int j = 0; j < 4; j++) {
            int gn = col0 + tn + j; if (gn >= Nn) continue;
            Rb[gm*Nn + gn] = acc[i][j];
        }
    }
}

// ---------------------------------------------------------------------------
// Complex 3x3 conv (cross-correlation, zero pad 1), per-batch weights.
// adj=1 applies conj(transpose(w,(0,2,1,4,3))): io swapped, HW swapped, imag negated.
// All z buffers have layout [B][4][511][511] regardless of active channel count.
// ---------------------------------------------------------------------------
__global__ void cconv_k(const float* __restrict__ xr, const float* __restrict__ xi,
                        const float* __restrict__ wr, const float* __restrict__ wi,
                        float* __restrict__ yr, float* __restrict__ yi,
                        int Cin, int Cout, int O0, int I0, int adj)
{
    int px = blockIdx.x*blockDim.x + threadIdx.x;
    int py = blockIdx.y*blockDim.y + threadIdx.y;
    int bz = blockIdx.z;
    int b = bz / Cout;
    int o = bz % Cout;
    if (px >= PP_ || py >= PP_) return;
    float ar = 0.f, ai = 0.f;
    for (int i = 0; i < Cin; i++) {
        const float* pr  = xr + (size_t)(b*4 + i)*PPP;
        const float* pim = xi + (size_t)(b*4 + i)*PPP;
        #pragma unroll
        for (int dy = 0; dy < 3; dy++) {
            int yy = py + dy - 1;
            if (yy < 0 || yy >= PP_) continue;
            #pragma unroll
            for (int dx = 0; dx < 3; dx++) {
                int xx = px + dx - 1;
                if (xx < 0 || xx >= PP_) continue;
                float cwr, cwi;
                if (!adj) {
                    int widx = ((b*O0 + o)*I0 + i)*9 + dy*3 + dx;
                    cwr = wr[widx]; cwi = wi[widx];
                } else {
                    int widx = ((b*O0 + i)*I0 + o)*9 + dx*3 + dy;
                    cwr = wr[widx]; cwi = -wi[widx];
                }
                float vr = pr[yy*PP_ + xx];
                float vi = pim[yy*PP_ + xx];
                ar += vr*cwr - vi*cwi;
                ai += vr*cwi + vi*cwr;
            }
        }
    }
    yr[(size_t)(b*4 + o)*PPP + py*PP_ + px] = ar;
    yi[(size_t)(b*4 + o)*PPP + py*PP_ + px] = ai;
}

// z(ch0) *= theta (in place)
__global__ void theta_k(float* __restrict__ zr, float* __restrict__ zi,
                        const float* __restrict__ tr, const float* __restrict__ ti)
{
    int idx = blockIdx.x*blockDim.x + threadIdx.x;
    if (idx >= BPP) return;
    int b = idx / PPP;
    int r = idx % PPP;
    size_t zo = (size_t)b*4*PPP + r;
    float a = zr[zo], c = zi[zo];
    float trv = tr[idx], tiv = ti[idx];
    zr[zo] = a*trv - c*tiv;
    zi[zo] = a*tiv + c*trv;
}

// x[interior] += coef<1 ? R0/coef : R1*coef
__global__ void update_x_k(float* __restrict__ x, const float* __restrict__ coef)
{
    int idx = blockIdx.x*blockDim.x + threadIdx.x;
    if (idx >= BMM) return;
    int i = idx % MM;
    int j = (idx / MM) % MM;
    int b = idx / MMM;
    float c = coef[idx];
    float e = (c < 1.f) ? d_R0[idx]/c : d_R1[idx]*c;
    x[b*NNN + (j+1)*NN_ + (i+1)] += e;
}

// ---------------------------------------------------------------------------
// Final residual norms (deterministic two-stage reduction, double accum)
// ---------------------------------------------------------------------------
__global__ void norm_partial_k(const float* __restrict__ f, const float* __restrict__ xin, int nblk)
{
    __shared__ double s1[256], s2[256];
    int tid = threadIdx.x;
    double ar = 0.0, af = 0.0;
    for (int idx = blockIdx.x*blockDim.x + tid; idx < BNN; idx += gridDim.x*blockDim.x) {
        int x = idx % NN_;
        int y = (idx / NN_) % NN_;
        int b = idx / NNN;
        float Ax = 0.f;
        if (y >= 1 && y < NN_-1 && x >= 1 && x < NN_-1) Ax = applyA(xin + b*NNN, b, y, x);
        float fv = f[idx];
        float r = fv - Ax;
        ar += (double)r*(double)r;
        af += (double)fv*(double)fv;
    }
    s1[tid] = ar; s2[tid] = af;
    __syncthreads();
    for (int s = 128; s > 0; s >>= 1) {
        if (tid < s) { s1[tid] += s1[tid+s]; s2[tid] += s2[tid+s]; }
        __syncthreads();
    }
    if (tid == 0) { d_part[blockIdx.x] = s1[0]; d_part[nblk + blockIdx.x] = s2[0]; }
}

__global__ void finalize_k(float* __restrict__ out, int nblk)
{
    __shared__ double s1[256], s2[256];
    int tid = threadIdx.x;
    double ar = 0.0, af = 0.0;
    for (int i = tid; i < nblk; i += 256) { ar += d_part[i]; af += d_part[nblk + i]; }
    s1[tid] = ar; s2[tid] = af;
    __syncthreads();
    for (int s = 128; s > 0; s >>= 1) {
        if (tid < s) { s1[tid] += s1[tid+s]; s2[tid] += s2[tid+s]; }
        __syncthreads();
    }
    if (tid == 0) out[0] = (float)sqrt(s1[0] / s2[0]);
}

// ---------------------------------------------------------------------------
// Host launch
// ---------------------------------------------------------------------------
extern "C" void kernel_launch(void* const* d_in, const int* in_sizes, int n_in,
                              void* d_out, int out_size)
{
    const float* f    = (const float*)d_in[0];
    const float* coef = (const float*)d_in[1];
    const float* w11r = (const float*)d_in[2];
    const float* w11i = (const float*)d_in[3];
    const float* w12r = (const float*)d_in[4];
    const float* w12i = (const float*)d_in[5];
    const float* w13r = (const float*)d_in[6];
    const float* w13i = (const float*)d_in[7];
    const float* t1r  = (const float*)d_in[8];
    const float* t1i  = (const float*)d_in[9];
    const float* w21r = (const float*)d_in[10];
    const float* w21i = (const float*)d_in[11];
    const float* w22r = (const float*)d_in[12];
    const float* w22i = (const float*)d_in[13];
    const float* w23r = (const float*)d_in[14];
    const float* w23i = (const float*)d_in[15];
    const float* t2r  = (const float*)d_in[16];
    const float* t2i  = (const float*)d_in[17];
    float* out = (float*)d_out;
    (void)in_sizes; (void)n_in; (void)out_size;

    float *p_x0, *p_x1, *p_r1, *p_Sf, *p_SfT, *p_Cm, *p_Sm, *p_CmT, *p_SmT;
    float *p_T1, *p_zar, *p_zai, *p_zbr, *p_zbi, *p_P, *p_Q, *p_R0, *p_R1;
    cudaGetSymbolAddress((void**)&p_x0,  d_x0);
    cudaGetSymbolAddress((void**)&p_x1,  d_x1);
    cudaGetSymbolAddress((void**)&p_r1,  d_r1);
    cudaGetSymbolAddress((void**)&p_Sf,  d_Sf);
    cudaGetSymbolAddress((void**)&p_SfT, d_SfT);
    cudaGetSymbolAddress((void**)&p_Cm,  d_Cm);
    cudaGetSymbolAddress((void**)&p_Sm,  d_Sm);
    cudaGetSymbolAddress((void**)&p_CmT, d_CmT);
    cudaGetSymbolAddress((void**)&p_SmT, d_SmT);
    cudaGetSymbolAddress((void**)&p_T1,  d_T1);
    cudaGetSymbolAddress((void**)&p_zar, d_zar);
    cudaGetSymbolAddress((void**)&p_zai, d_zai);
    cudaGetSymbolAddress((void**)&p_zbr, d_zbr);
    cudaGetSymbolAddress((void**)&p_zbi, d_zbi);
    cudaGetSymbolAddress((void**)&p_P,   d_Pm);
    cudaGetSymbolAddress((void**)&p_Q,   d_Qm);
    cudaGetSymbolAddress((void**)&p_R0,  d_R0);
    cudaGetSymbolAddress((void**)&p_R1,  d_R1);

    // trig + stencil
    {
        dim3 b2(16,16), g2((PP_+15)/16, (PP_+15)/16);
        trig_init_k<<<g2, b2>>>();
    }
    stencil_k<<<(BMM+255)/256, 256>>>(coef);

    // 10 Jacobi sweeps from x=0 (K=1: epoch==1 in setup_inputs)
    fill0_k<<<(BNN+255)/256, 256>>>(p_x0, BNN);
    const float wrelax = 40.0f / 512.0f;
    float* xa = p_x0;
    float* xb = p_x1;
    for (int t = 0; t < 10; t++) {
        jacobi_k<<<(BNN+255)/256, 256>>>(f, xa, xb, wrelax);
        float* tmp = xa; xa = xb; xb = tmp;
    }
    // residual interior
    resid_k<<<(BMM+255)/256, 256>>>(f, xa);

    dim3 cb(32,8);
    dim3 cg4((PP_+31)/32, (PP_+7)/8, BB*4);
    dim3 cg1((PP_+31)/32, (PP_+7)/8, BB*1);

    for (int call = 0; call < 2; call++) {
        const float *war, *wai, *wbr_, *wbi_, *wcr, *wci, *thr_, *thi_;
        if (call == 0) { war=w11r; wai=w11i; wbr_=w12r; wbi_=w12i; wcr=w13r; wci=w13i; thr_=t1r; thi_=t1i; }
        else           { war=w21r; wai=w21i; wbr_=w22r; wbi_=w22i; wcr=w23r; wci=w23i; thr_=t2r; thi_=t2i; }

        // forward DST: rh = -(1/511^2) * Sf @ r1 @ Sf^T  -> zA real ch0, imag=0
        {
            dim3 g1((510+GBN-1)/GBN, (511+GBM-1)/GBM, BB);
            gemm_k<<<g1, 256>>>(p_Sf, 0, p_r1, MMM, p_T1, PP_*MM, 511, 510, 510, 1.0f);
            dim3 g2((511+GBN-1)/GBN, (511+GBM-1)/GBM, BB);
            gemm_k<<<g2, 256>>>(p_T1, PP_*MM, p_SfT, 0, p_zar, 4*PPP, 511, 511, 510,
                                -1.0f/(511.0f*511.0f));
            zero_ch0_k<<<(BPP+255)/256, 256>>>(p_zai);
        }

        // conv chain: 1->4->4->1, theta, then adjoints 1->4->4->1
        cconv_k<<<cg4, cb>>>(p_zar, p_zai, war, wai, p_zbr, p_zbi, 1, 4, 4, 1, 0);
        cconv_k<<<cg4, cb>>>(p_zbr, p_zbi, wbr_, wbi_, p_zar, p_zai, 4, 4, 4, 4, 0);
        cconv_k<<<cg1, cb>>>(p_zar, p_zai, wcr, wci, p_zbr, p_zbi, 4, 1, 1, 4, 0);
        theta_k<<<(BPP+255)/256, 256>>>(p_zbr, p_zbi, thr_, thi_);
        cconv_k<<<cg4, cb>>>(p_zbr, p_zbi, wcr, wci, p_zar, p_zai, 1, 4, 1, 4, 1);
        cconv_k<<<cg4, cb>>>(p_zar, p_zai, wbr_, wbi_, p_zbr, p_zbi, 4, 4, 4, 4, 1);
        cconv_k<<<cg1, cb>>>(p_zbr, p_zbi, war, wai, p_zar, p_zai, 4, 1, 4, 1, 1);

        // inverse: P = C a + S b, Q = C b - S a ; ReF = P C^T + Q S^T
        {
            dim3 g1((511+GBN-1)/GBN, (510+GBM-1)/GBM, BB);
            gemm_dualL_k<<<g1, 256>>>(p_Cm, p_Sm, p_zar, 4*PPP, p_zai, 4*PPP,
                                      p_P, MM*PP_, p_Q, MM*PP_, 510, 511, 511);
            dim3 g2((510+GBN-1)/GBN, (510+GBM-1)/GBM, BB);
            gemm_dualR_k<<<g2, 256>>>(p_P, MM*PP_, p_Q, MM*PP_, p_CmT, p_SmT,
                                      (call == 0 ? p_R0 : p_R1), MMM, 510, 510, 511);
        }
    }

    // x += pad(e1+e2), then ||f - A x|| / ||f||
    update_x_k<<<(BMM+255)/256, 256>>>(xa, coef);
    const int nblk = 1024;
    norm_partial_k<<<nblk, 256>>>(f, xa, nblk);
    finalize_k<<<1, 256>>>(out, nblk);
}

// round 3
// speedup vs baseline: 1.4235x; 1.4235x over previous
#include <cuda_runtime.h>
#include <math.h>

// ---------------------------------------------------------------------------
// Problem constants
// ---------------------------------------------------------------------------
#define BB   8
#define NN_  512
#define MM   510
#define PP_  511
#define PI_F 3.14159265358979323846f

#define NNN   (NN_*NN_)
#define BNN   (BB*NNN)
#define MMM   (MM*MM)
#define BMM   (BB*MMM)

// padded GEMM dimension
#define GD    512
#define GDD   (GD*GD)
#define BGDD  (BB*GDD)

// conv buffer layout: halo'd planes, stride 520, 514 rows, domain at (+1,+4)
#define Z_W   520
#define Z_H   514
#define PLANE (Z_H*Z_W)
#define DOFF  (Z_W + 4)

// ---------------------------------------------------------------------------
// Static device scratch
// ---------------------------------------------------------------------------
__device__ float d_x0[BNN];
__device__ float d_x1[BNN];
__device__ float d_st[5*BMM];
__device__ float d_Sf [GDD];
__device__ float d_SfT[GDD];
__device__ float d_Cm [GDD];
__device__ float d_Sm [GDD];
__device__ float d_CpS[GDD];
__device__ float d_CmT[GDD];
__device__ float d_SmT[GDD];
__device__ float d_r1[BGDD];
__device__ float d_T1[BGDD];          // forward stage-1; reused as diff buffer later
__device__ float d_rh[BB*PLANE];      // shared DST result (real)
__device__ float d_zar[BB*4*PLANE];
__device__ float d_zai[BB*4*PLANE];
__device__ float d_zbr[BB*4*PLANE];
__device__ float d_zbi[BB*4*PLANE];
__device__ float d_m1[BGDD];
__device__ float d_m2[BGDD];
__device__ float d_m3[BGDD];
__device__ float d_Pm[BGDD];
__device__ float d_Qm[BGDD];
__device__ float d_R0[BGDD];
__device__ float d_R1[BGDD];
__device__ double d_part[2*1024];

// ---------------------------------------------------------------------------
// Trig matrices, padded to 512x512 with zeros
// ---------------------------------------------------------------------------
__global__ void trig_init_k()
{
    int x = blockIdx.x*blockDim.x + threadIdx.x;
    int y = blockIdx.y*blockDim.y + threadIdx.y;
    if (x >= GD || y >= GD) return;
    // Sf[u=y][j=x], u<511, j<510
    float sf = 0.f;
    if (y < PP_ && x < MM) {
        int t = (x+1) * (y-255);
        int m = t % 1022; if (m < 0) m += 1022;
        sf = sinf((float)m * (PI_F/511.0f));
    }
    d_Sf [y*GD + x] = sf;
    d_SfT[x*GD + y] = sf;
    // Cm[n=y][u=x], n<510, u<511
    float c = 0.f, s = 0.f;
    if (y < MM && x < PP_) {
        int t = y * (x - 255);
        int m = t % 1022; if (m < 0) m += 1022;
        float ang = (float)m * (PI_F/511.0f);
        c = cosf(ang); s = sinf(ang);
    }
    d_Cm [y*GD + x] = c;
    d_Sm [y*GD + x] = s;
    d_CpS[y*GD + x] = c + s;
    d_CmT[x*GD + y] = c;
    d_SmT[x*GD + y] = s;
}

// ---------------------------------------------------------------------------
// Stencil coefficients
// ---------------------------------------------------------------------------
__global__ void stencil_k(const float* __restrict__ coef)
{
    int idx = blockIdx.x*blockDim.x + threadIdx.x;
    if (idx >= BMM) return;
    int i = idx % MM;
    int j = (idx / MM) % MM;
    int b = idx / MMM;
    const float* cb = coef + b*MMM;
    float a   = cb[j*MM + i];
    float aw  = cb[j*MM + (i>0    ? i-1 : 0   )];
    float ae  = cb[j*MM + (i<MM-1 ? i+1 : MM-1)];
    float an  = cb[(j<MM-1 ? j+1 : MM-1)*MM + i];
    float as_ = cb[(j>0    ? j-1 : 0   )*MM + i];
    float sw = -2.f*aw *a/(aw +a);
    float se = -2.f*ae *a/(ae +a);
    float sn = -2.f*an *a/(an +a);
    float ss = -2.f*as_*a/(as_+a);
    d_st[0*BMM+idx] = sw;
    d_st[1*BMM+idx] = se;
    d_st[2*BMM+idx] = sn;
    d_st[3*BMM+idx] = ss;
    d_st[4*BMM+idx] = -(sw+se+sn+ss);
}

__device__ __forceinline__ float applyA(const float* __restrict__ xb, int b, int y, int x)
{
    int s = b*MMM + (y-1)*MM + (x-1);
    return d_st[3*BMM+s]*xb[(y-1)*NN_+x]
         + d_st[0*BMM+s]*xb[y*NN_+x-1]
         + d_st[4*BMM+s]*xb[y*NN_+x]
         + d_st[1*BMM+s]*xb[y*NN_+x+1]
         + d_st[2*BMM+s]*xb[(y+1)*NN_+x];
}

__global__ void fill0_k(float* __restrict__ p, int n)
{
    int idx = blockIdx.x*blockDim.x + threadIdx.x;
    if (idx < n) p[idx] = 0.f;
}

// zero halo cells of conv-layout planes (rows 0,512,513 full; side cols for rows 1..511)
__global__ void border_k(float* __restrict__ buf)
{
    float* pl = buf + (size_t)blockIdx.x * PLANE;
    const int nA = 3*Z_W;          // rows 0, 512, 513
    const int nB = 511*9;          // rows 1..511, cols {0..3, 515..519}
    for (int i = threadIdx.x; i < nA + nB; i += blockDim.x) {
        int off;
        if (i < nA) {
            int which = i / Z_W;
            int row = (which == 0) ? 0 : (which == 1 ? 512 : 513);
            off = row*Z_W + (i % Z_W);
        } else {
            int j = i - nA;
            int row = 1 + j/9;
            int c9 = j % 9;
            int col = (c9 < 4) ? c9 : (511 + c9);   // 515..519
            off = row*Z_W + col;
        }
        pl[off] = 0.f;
    }
}

__global__ void jacobi_k(const float* __restrict__ f, const float* __restrict__ xin,
                         float* __restrict__ xout, float w)
{
    int idx = blockIdx.x*blockDim.x + threadIdx.x;
    if (idx >= BNN) return;
    int x = idx % NN_;
    int y = (idx / NN_) % NN_;
    int b = idx / NNN;
    const float* xb = xin + b*NNN;
    float Ax = 0.f;
    if (y >= 1 && y < NN_-1 && x >= 1 && x < NN_-1) Ax = applyA(xb, b, y, x);
    xout[idx] = xin[idx] + w*(f[idx] - Ax);
}

// residual interior -> padded 512x512 per batch
__global__ void resid_k(const float* __restrict__ f, const float* __restrict__ xin)
{
    int idx = blockIdx.x*blockDim.x + threadIdx.x;
    if (idx >= BMM) return;
    int i = idx % MM;
    int j = (idx / MM) % MM;
    int b = idx / MMM;
    int y = j+1, x = i+1;
    d_r1[b*GDD + j*GD + i] = f[b*NNN + y*NN_ + x] - applyA(xin + b*NNN, b, y, x);
}

// ---------------------------------------------------------------------------
// 512^3 SGEMM, 128x128x8 tile, 8x8 microtile, packed fma.rn.f32x2
// C = alpha*(A@B) + (beta ? C : 0)
// ---------------------------------------------------------------------------
__global__ __launch_bounds__(256, 2) void gemm512_k(
    const float* __restrict__ A, long long sA, int lda,
    const float* __restrict__ B, long long sB, int ldb,
    float* __restrict__ C, long long sC, int ldc,
    float alpha, int beta)
{
    const float* Ab = A + blockIdx.z*sA;
    const float* Bb = B + blockIdx.z*sB;
    float*       Cb = C + blockIdx.z*sC;
    __shared__ float As[8][132];
    __shared__ float Bs[8][128];
    int tid = threadIdx.x;
    int arow = tid >> 1;
    int acol = (tid & 1) << 2;
    int brow = tid >> 5;
    int bcol = (tid & 31) << 2;
    const int m0 = blockIdx.y * 128;
    const int n0 = blockIdx.x * 128;
    int row = (tid >> 4) << 3;
    int col = (tid & 15) << 3;

    unsigned long long acc[8][4];
    #pragma unroll
    for (int i = 0; i < 8; i++)
        #pragma unroll
        for (int j = 0; j < 4; j++) acc[i][j] = 0ull;

    const float* Aptr = Ab + (size_t)(m0+arow)*lda + acol;
    const float* Bptr = Bb + (size_t)brow*ldb + n0 + bcol;

    float4 av4 = *(const float4*)(Aptr);
    float4 bv4 = *(const float4*)(Bptr);

    for (int k0 = 0; k0 < 512; k0 += 8) {
        As[acol+0][arow] = av4.x;
        As[acol+1][arow] = av4.y;
        As[acol+2][arow] = av4.z;
        As[acol+3][arow] = av4.w;
        *(float4*)&Bs[brow][bcol] = bv4;
        __syncthreads();
        if (k0 + 8 < 512) {
            av4 = *(const float4*)(Aptr + (k0 + 8));
            bv4 = *(const float4*)(Bptr + (size_t)(k0 + 8)*ldb);
        }
        #pragma unroll
        for (int k = 0; k < 8; k++) {
            float a_[8];
            #pragma unroll
            for (int i = 0; i < 4; i++) {
                float2 t = *(const float2*)&As[k][row + 2*i];
                a_[2*i] = t.x; a_[2*i+1] = t.y;
            }
            unsigned long long b2[4];
            #pragma unroll
            for (int j = 0; j < 4; j++)
                b2[j] = *(const unsigned long long*)&Bs[k][col + 2*j];
            #pragma unroll
            for (int i = 0; i < 8; i++) {
                unsigned long long a2;
                asm("mov.b64 %0, {%1, %1};" : "=l"(a2) : "f"(a_[i]));
                #pragma unroll
                for (int j = 0; j < 4; j++)
                    asm("fma.rn.f32x2 %0, %1, %2, %0;"
                        : "+l"(acc[i][j]) : "l"(a2), "l"(b2[j]));
            }
        }
        __syncthreads();
    }
    #pragma unroll
    for (int i = 0; i < 8; i++) {
        float* crow = Cb + (size_t)(m0+row+i)*ldc + n0 + col;
        #pragma unroll
        for (int j = 0; j < 4; j++) {
            float lo, hi;
            asm("mov.b64 {%0, %1}, %2;" : "=f"(lo), "=f"(hi) : "l"(acc[i][j]));
            float2 o;
            if (beta) {
                o = *(const float2*)&crow[2*j];
                o.x += alpha*lo; o.y += alpha*hi;
            } else {
                o.x = alpha*lo; o.y = alpha*hi;
            }
            *(float2*)&crow[2*j] = o;
        }
    }
}

// ---------------------------------------------------------------------------
// Tiled complex 3x3 conv. Block (32,8): 32x32 output tile, 4 y-pixels/thread.
// Halo'd layout means zero bounds checks on reads.
// ---------------------------------------------------------------------------
template<int CIN, int COUT, bool ADJ, bool REALIN, bool THETA>
__global__ __launch_bounds__(256) void conv_k(
    const float* __restrict__ xr, const float* __restrict__ xi,
    long long xbs, long long xcs,
    const float* __restrict__ wr, const float* __restrict__ wi,
    float* __restrict__ yr, float* __restrict__ yi,
    const float* __restrict__ tr, const float* __restrict__ ti,
    int O0, int I0)
{
    const int NPL = CIN * (REALIN ? 1 : 2);
    __shared__ float sv[CIN*(REALIN?1:2)][34*34];
    __shared__ float swr[COUT*CIN*9];
    __shared__ float swi[COUT*CIN*9];

    int tid = threadIdx.y*32 + threadIdx.x;
    int b = blockIdx.z;
    int by = blockIdx.y, bx = blockIdx.x;

    // weights -> shared (adjoint transform applied at load)
    for (int t = tid; t < COUT*CIN*9; t += 256) {
        int o = t / (CIN*9);
        int i = (t / 9) % CIN;
        int tap = t % 9;
        int dy = tap / 3, dx = tap % 3;
        int widx;
        float sgn;
        if (!ADJ) { widx = ((b*O0 + o)*I0 + i)*9 + dy*3 + dx; sgn = 1.f; }
        else      { widx = ((b*O0 + i)*I0 + o)*9 + dx*3 + dy; sgn = -1.f; }
        swr[t] = wr[widx];
        swi[t] = sgn * wi[widx];
    }

    // input tiles -> shared
    for (int p = 0; p < NPL; p++) {
        int ch   = REALIN ? p : (p >> 1);
        bool im  = REALIN ? false : (p & 1);
        const float* src = (im ? xi : xr) + b*xbs + ch*xcs;
        for (int idx = tid; idx < 34*34; idx += 256) {
            int r = idx / 34, c = idx % 34;
            int gy = by*32 + r - 1;           // -1 .. 512 -> buffer rows 0..513
            int gxo = bx*32 + c + 3;          // buffer col = gx-1+4
            sv[p][idx] = src[(size_t)(gy+1)*Z_W + gxo];
        }
    }
    __syncthreads();

    int tx = threadIdx.x;
    int r0 = threadIdx.y * 4;

    float accR[COUT][4];
    float accI[COUT][4];
    #pragma unroll
    for (int o = 0; o < COUT; o++)
        #pragma unroll
        for (int p = 0; p < 4; p++) { accR[o][p] = 0.f; accI[o][p] = 0.f; }

    #pragma unroll
    for (int i = 0; i < CIN; i++) {
        float vr[6][3], vi[6][3];
        #pragma unroll
        for (int ry = 0; ry < 6; ry++)
            #pragma unroll
            for (int cx = 0; cx < 3; cx++) {
                int sidx = (r0+ry)*34 + tx + cx;
                if (REALIN) { vr[ry][cx] = sv[i][sidx]; vi[ry][cx] = 0.f; }
                else        { vr[ry][cx] = sv[2*i][sidx]; vi[ry][cx] = sv[2*i+1][sidx]; }
            }
        #pragma unroll
        for (int o = 0; o < COUT; o++) {
            #pragma unroll
            for (int dy = 0; dy < 3; dy++)
                #pragma unroll
                for (int dx = 0; dx < 3; dx++) {
                    float wrv = swr[(o*CIN + i)*9 + dy*3 + dx];
                    float wiv = swi[(o*CIN + i)*9 + dy*3 + dx];
                    #pragma unroll
                    for (int p = 0; p < 4; p++) {
                        float a = vr[p+dy][dx];
                        float c = vi[p+dy][dx];
                        accR[o][p] += a*wrv - c*wiv;
                        accI[o][p] += a*wiv + c*wrv;
                    }
                }
        }
    }

    int gx = bx*32 + tx;
    if (gx >= PP_) return;
    #pragma unroll
    for (int p = 0; p < 4; p++) {
        int gy = by*32 + r0 + p;
        if (gy >= PP_) continue;
        size_t doff = (size_t)(gy+1)*Z_W + gx + 4;
        #pragma unroll
        for (int o = 0; o < COUT; o++) {
            float ar = accR[o][p], ai = accI[o][p];
            if (THETA) {
                float trv = tr[(size_t)b*PP_*PP_ + gy*PP_ + gx];
                float tiv = ti[(size_t)b*PP_*PP_ + gy*PP_ + gx];
                float nr = ar*trv - ai*tiv;
                float ni = ar*tiv + ai*trv;
                ar = nr; ai = ni;
            }
            yr[(size_t)(b*4 + o)*PLANE + doff] = ar;
            yi[(size_t)(b*4 + o)*PLANE + doff] = ai;
        }
    }
}

// diff for 3M trick: T1 = imag - real (ch0 domain, padded-512 out)
__global__ void diff_k(const float* __restrict__ zr, const float* __restrict__ zi)
{
    int idx = blockIdx.x*blockDim.x + threadIdx.x;
    if (idx >= BGDD) return;
    int i = idx % GD;
    int j = (idx / GD) % GD;
    int b = idx / GDD;
    size_t zo = (size_t)b*4*PLANE + DOFF + (size_t)j*Z_W + i;
    d_T1[idx] = zi[zo] - zr[zo];
}

// P = m1+m2 ; Q = m1-m2+m3
__global__ void combine_k()
{
    int idx = blockIdx.x*blockDim.x + threadIdx.x;
    if (idx >= BGDD) return;
    float a = d_m1[idx], b = d_m2[idx], c = d_m3[idx];
    d_Pm[idx] = a + b;
    d_Qm[idx] = a - b + c;
}

// x[interior] += coef<1 ? R0/coef : R1*coef
__global__ void update_x_k(float* __restrict__ x, const float* __restrict__ coef)
{
    int idx = blockIdx.x*blockDim.x + threadIdx.x;
    if (idx >= BMM) return;
    int i = idx % MM;
    int j = (idx / MM) % MM;
    int b = idx / MMM;
    float c = coef[idx];
    int ridx = b*GDD + j*GD + i;
    float e = (c < 1.f) ? d_R0[ridx]/c : d_R1[ridx]*c;
    x[b*NNN + (j+1)*NN_ + (i+1)] += e;
}

// ---------------------------------------------------------------------------
// Final norms
// ---------------------------------------------------------------------------
__global__ void norm_partial_k(const float* __restrict__ f, const float* __restrict__ xin, int nblk)
{
    __shared__ double s1[256], s2[256];
    int tid = threadIdx.x;
    double ar = 0.0, af = 0.0;
    for (int idx = blockIdx.x*blockDim.x + tid; idx < BNN; idx += gridDim.x*blockDim.x) {
        int x = idx % NN_;
        int y = (idx / NN_) % NN_;
        int b = idx / NNN;
        float Ax = 0.f;
        if (y >= 1 && y < NN_-1 && x >= 1 && x < NN_-1) Ax = applyA(xin + b*NNN, b, y, x);
        float fv = f[idx];
        float r = fv - Ax;
        ar += (double)r*(double)r;
        af += (double)fv*(double)fv;
    }
    s1[tid] = ar; s2[tid] = af;
    __syncthreads();
    for (int s = 128; s > 0; s >>= 1) {
        if (tid < s) { s1[tid] += s1[tid+s]; s2[tid] += s2[tid+s]; }
        __syncthreads();
    }
    if (tid == 0) { d_part[blockIdx.x] = s1[0]; d_part[nblk + blockIdx.x] = s2[0]; }
}

__global__ void finalize_k(float* __restrict__ out, int nblk)
{
    __shared__ double s1[256], s2[256];
    int tid = threadIdx.x;
    double ar = 0.0, af = 0.0;
    for (int i = tid; i < nblk; i += 256) { ar += d_part[i]; af += d_part[nblk + i]; }
    s1[tid] = ar; s2[tid] = af;
    __syncthreads();
    for (int s = 128; s > 0; s >>= 1) {
        if (tid < s) { s1[tid] += s1[tid+s]; s2[tid] += s2[tid+s]; }
        __syncthreads();
    }
    if (tid == 0) out[0] = (float)sqrt(s1[0] / s2[0]);
}

// ---------------------------------------------------------------------------
// Host launch
// ---------------------------------------------------------------------------
extern "C" void kernel_launch(void* const* d_in, const int* in_sizes, int n_in,
                              void* d_out, int out_size)
{
    const float* f    = (const float*)d_in[0];
    const float* coef = (const float*)d_in[1];
    const float* w11r = (const float*)d_in[2];
    const float* w11i = (const float*)d_in[3];
    const float* w12r = (const float*)d_in[4];
    const float* w12i = (const float*)d_in[5];
    const float* w13r = (const float*)d_in[6];
    const float* w13i = (const float*)d_in[7];
    const float* t1r  = (const float*)d_in[8];
    const float* t1i  = (const float*)d_in[9];
    const float* w21r = (const float*)d_in[10];
    const float* w21i = (const float*)d_in[11];
    const float* w22r = (const float*)d_in[12];
    const float* w22i = (const float*)d_in[13];
    const float* w23r = (const float*)d_in[14];
    const float* w23i = (const float*)d_in[15];
    const float* t2r  = (const float*)d_in[16];
    const float* t2i  = (const float*)d_in[17];
    float* out = (float*)d_out;
    (void)in_sizes; (void)n_in; (void)out_size;

    float *p_x0, *p_x1, *p_r1, *p_T1, *p_rh;
    float *p_Sf, *p_SfT, *p_Cm, *p_Sm, *p_CpS, *p_CmT, *p_SmT;
    float *p_zar, *p_zai, *p_zbr, *p_zbi;
    float *p_m1, *p_m2, *p_m3, *p_P, *p_Q, *p_R0, *p_R1;
    cudaGetSymbolAddress((void**)&p_x0,  d_x0);
    cudaGetSymbolAddress((void**)&p_x1,  d_x1);
    cudaGetSymbolAddress((void**)&p_r1,  d_r1);
    cudaGetSymbolAddress((void**)&p_T1,  d_T1);
    cudaGetSymbolAddress((void**)&p_rh,  d_rh);
    cudaGetSymbolAddress((void**)&p_Sf,  d_Sf);
    cudaGetSymbolAddress((void**)&p_SfT, d_SfT);
    cudaGetSymbolAddress((void**)&p_Cm,  d_Cm);
    cudaGetSymbolAddress((void**)&p_Sm,  d_Sm);
    cudaGetSymbolAddress((void**)&p_CpS, d_CpS);
    cudaGetSymbolAddress((void**)&p_CmT, d_CmT);
    cudaGetSymbolAddress((void**)&p_SmT, d_SmT);
    cudaGetSymbolAddress((void**)&p_zar, d_zar);
    cudaGetSymbolAddress((void**)&p_zai, d_zai);
    cudaGetSymbolAddress((void**)&p_zbr, d_zbr);
    cudaGetSymbolAddress((void**)&p_zbi, d_zbi);
    cudaGetSymbolAddress((void**)&p_m1,  d_m1);
    cudaGetSymbolAddress((void**)&p_m2,  d_m2);
    cudaGetSymbolAddress((void**)&p_m3,  d_m3);
    cudaGetSymbolAddress((void**)&p_P,   d_Pm);
    cudaGetSymbolAddress((void**)&p_Q,   d_Qm);
    cudaGetSymbolAddress((void**)&p_R0,  d_R0);
    cudaGetSymbolAddress((void**)&p_R1,  d_R1);

    // init: trig, stencil, padded-r1 clear, halo clears
    {
        dim3 b2(16,16), g2((GD+15)/16, (GD+15)/16);
        trig_init_k<<<g2, b2>>>();
    }
    stencil_k<<<(BMM+255)/256, 256>>>(coef);
    fill0_k<<<(BGDD+255)/256, 256>>>(p_r1, BGDD);
    border_k<<<BB, 256>>>(p_rh);
    border_k<<<BB*4, 256>>>(p_zar);
    border_k<<<BB*4, 256>>>(p_zai);
    border_k<<<BB*4, 256>>>(p_zbr);
    border_k<<<BB*4, 256>>>(p_zbi);

    // 10 Jacobi sweeps from x=0  (epoch==1 -> K=1)
    fill0_k<<<(BNN+255)/256, 256>>>(p_x0, BNN);
    const float wrelax = 40.0f / 512.0f;
    float* xa = p_x0;
    float* xb = p_x1;
    for (int t = 0; t < 10; t++) {
        jacobi_k<<<(BNN+255)/256, 256>>>(f, xa, xb, wrelax);
        float* tmp = xa; xa = xb; xb = tmp;
    }
    resid_k<<<(BMM+255)/256, 256>>>(f, xa);

    dim3 gg(4,4,BB);
    // shared forward DST: rh = -(1/511^2) * Sf @ r1 @ SfT
    gemm512_k<<<gg, 256>>>(p_Sf, 0, GD,  p_r1, GDD, GD,  p_T1, GDD, GD, 1.0f, 0);
    gemm512_k<<<gg, 256>>>(p_T1, GDD, GD, p_SfT, 0, GD,
                           p_rh + DOFF, (long long)PLANE, Z_W,
                           -1.0f/(511.0f*511.0f), 0);

    dim3 cg(16,16,BB), cbk(32,8);
    long long cb_bs = 4LL*PLANE, cb_cs = PLANE;

    for (int call = 0; call < 2; call++) {
        const float *war, *wai, *wbr_, *wbi_, *wcr, *wci, *thr_, *thi_;
        if (call == 0) { war=w11r; wai=w11i; wbr_=w12r; wbi_=w12i; wcr=w13r; wci=w13i; thr_=t1r; thi_=t1i; }
        else           { war=w21r; wai=w21i; wbr_=w22r; wbi_=w22i; wcr=w23r; wci=w23i; thr_=t2r; thi_=t2i; }

        // conv chain
        conv_k<1,4,false,true ,false><<<cg,cbk>>>(p_rh, nullptr, (long long)PLANE, 0,
                                                  war, wai, p_zbr, p_zbi, nullptr, nullptr, 4, 1);
        conv_k<4,4,false,false,false><<<cg,cbk>>>(p_zbr, p_zbi, cb_bs, cb_cs,
                                                  wbr_, wbi_, p_zar, p_zai, nullptr, nullptr, 4, 4);
        conv_k<4,1,false,false,true ><<<cg,cbk>>>(p_zar, p_zai, cb_bs, cb_cs,
                                                  wcr, wci, p_zbr, p_zbi, thr_, thi_, 1, 4);
        conv_k<1,4,true ,false,false><<<cg,cbk>>>(p_zbr, p_zbi, cb_bs, cb_cs,
                                                  wcr, wci, p_zar, p_zai, nullptr, nullptr, 1, 4);
        conv_k<4,4,true ,false,false><<<cg,cbk>>>(p_zar, p_zai, cb_bs, cb_cs,
                                                  wbr_, wbi_, p_zbr, p_zbi, nullptr, nullptr, 4, 4);
        conv_k<4,1,true ,false,false><<<cg,cbk>>>(p_zbr, p_zbi, cb_bs, cb_cs,
                                                  war, wai, p_zar, p_zai, nullptr, nullptr, 4, 1);

        // inverse via 3M: m1=C@a, m2=S@b, m3=(C+S)@(b-a); P=m1+m2, Q=m1-m2+m3
        diff_k<<<(BGDD+255)/256, 256>>>(p_zar, p_zai);
        gemm512_k<<<gg,256>>>(p_Cm , 0, GD, p_zar + DOFF, 4LL*PLANE, Z_W, p_m1, GDD, GD, 1.0f, 0);
        gemm512_k<<<gg,256>>>(p_Sm , 0, GD, p_zai + DOFF, 4LL*PLANE, Z_W, p_m2, GDD, GD, 1.0f, 0);
        gemm512_k<<<gg,256>>>(p_CpS, 0, GD, p_T1, GDD, GD,                p_m3, GDD, GD, 1.0f, 0);
        combine_k<<<(BGDD+255)/256, 256>>>();
        float* pR = (call == 0) ? p_R0 : p_R1;
        gemm512_k<<<gg,256>>>(p_P, GDD, GD, p_CmT, 0, GD, pR, GDD, GD, 1.0f, 0);
        gemm512_k<<<gg,256>>>(p_Q, GDD, GD, p_SmT, 0, GD, pR, GDD, GD, 1.0f, 1);
    }

    update_x_k<<<(BMM+255)/256, 256>>>(xa, coef);
    const int nblk = 1024;
    norm_partial_k<<<nblk, 256>>>(f, xa, nblk);
    finalize_k<<<1, 256>>>(out, nblk);
}

// round 4
// speedup vs baseline: 1.4304x; 1.0048x over previous
#include <cuda_runtime.h>
#include <math.h>

// ---------------------------------------------------------------------------
// Problem constants
// ---------------------------------------------------------------------------
#define BB   8
#define NN_  512
#define MM   510
#define PP_  511
#define PI_F 3.14159265358979323846f

#define NNN   (NN_*NN_)
#define BNN   (BB*NNN)
#define MMM   (MM*MM)
#define BMM   (BB*MMM)

// padded GEMM dimension
#define GD    512
#define GDD   (GD*GD)
#define BGDD  (BB*GDD)
#define BG2   (2*BGDD)          // both calls

// conv buffer layout: halo'd planes, stride 520, 514 rows, domain at (+1,+4)
#define Z_W   520
#define Z_H   514
#define PLANE (Z_H*Z_W)
#define DOFF  (Z_W + 4)

// ---------------------------------------------------------------------------
// Static device scratch
// ---------------------------------------------------------------------------
__device__ float d_x0[BNN];
__device__ float d_x1[BNN];
__device__ float d_Sf [GDD];
__device__ float d_SfT[GDD];
__device__ float d_Cm [GDD];
__device__ float d_Sm [GDD];
__device__ float d_CpS[GDD];
__device__ float d_CmT[GDD];
__device__ float d_SmT[GDD];
__device__ float d_r1[BGDD];
__device__ float d_T1[BG2];           // forward stage-1 temp (first 8) / diff (16)
__device__ float d_rh[BB*PLANE];      // shared DST result (real)
__device__ float d_zar[16*4*PLANE];   // 16 = batch(8) x call(2)
__device__ float d_zai[16*4*PLANE];
__device__ float d_zbr[16*4*PLANE];
__device__ float d_zbi[16*4*PLANE];
__device__ float d_m1[BG2];
__device__ float d_m2[BG2];
__device__ float d_m3[BG2];
__device__ float d_Pm[BG2];
__device__ float d_Qm[BG2];
__device__ float d_R[BG2];            // call 0 -> slots 0..7, call 1 -> 8..15
__device__ double d_part[2*1024];

// ---------------------------------------------------------------------------
// Trig matrices, padded to 512x512 with zeros
// ---------------------------------------------------------------------------
__global__ void trig_init_k()
{
    int x = blockIdx.x*blockDim.x + threadIdx.x;
    int y = blockIdx.y*blockDim.y + threadIdx.y;
    if (x >= GD || y >= GD) return;
    float sf = 0.f;
    if (y < PP_ && x < MM) {
        int t = (x+1) * (y-255);
        int m = t % 1022; if (m < 0) m += 1022;
        sf = sinf((float)m * (PI_F/511.0f));
    }
    d_Sf [y*GD + x] = sf;
    d_SfT[x*GD + y] = sf;
    float c = 0.f, s = 0.f;
    if (y < MM && x < PP_) {
        int t = y * (x - 255);
        int m = t % 1022; if (m < 0) m += 1022;
        float ang = (float)m * (PI_F/511.0f);
        c = cosf(ang); s = sinf(ang);
    }
    d_Cm [y*GD + x] = c;
    d_Sm [y*GD + x] = s;
    d_CpS[y*GD + x] = c + s;
    d_CmT[x*GD + y] = c;
    d_SmT[x*GD + y] = s;
}

// ---------------------------------------------------------------------------
// On-the-fly stencil application: A(x) at interior (y,x), y,x in [1,511)
// ---------------------------------------------------------------------------
__device__ __forceinline__ float applyA(const float* __restrict__ xb,
                                        const float* __restrict__ cb,
                                        int y, int x)
{
    int i = x-1, j = y-1;
    float a   = cb[j*MM + i];
    float aw  = cb[j*MM + (i>0    ? i-1 : 0   )];
    float ae  = cb[j*MM + (i<MM-1 ? i+1 : MM-1)];
    float an  = cb[(j<MM-1 ? j+1 : MM-1)*MM + i];
    float as_ = cb[(j>0    ? j-1 : 0   )*MM + i];
    float sw = __fdividef(-2.f*aw *a, aw +a);
    float se = __fdividef(-2.f*ae *a, ae +a);
    float sn = __fdividef(-2.f*an *a, an +a);
    float ss = __fdividef(-2.f*as_*a, as_+a);
    float sc = -(sw+se+sn+ss);
    return ss*xb[(y-1)*NN_+x] + sw*xb[y*NN_+x-1] + sc*xb[y*NN_+x]
         + se*xb[y*NN_+x+1]   + sn*xb[(y+1)*NN_+x];
}

__global__ void fill0_k(float* __restrict__ p, int n)
{
    int idx = blockIdx.x*blockDim.x + threadIdx.x;
    if (idx < n) p[idx] = 0.f;
}

// first Jacobi sweep from x=0: x = w*f
__global__ void first_k(const float* __restrict__ f, float* __restrict__ xout, float w)
{
    int idx = blockIdx.x*blockDim.x + threadIdx.x;
    if (idx < BNN) xout[idx] = w*f[idx];
}

// zero halo cells of conv-layout planes
__global__ void border_k(float* __restrict__ buf)
{
    float* pl = buf + (size_t)blockIdx.x * PLANE;
    const int nA = 3*Z_W;          // rows 0, 512, 513
    const int nB = 511*9;          // rows 1..511, cols {0..3, 515..519}
    for (int i = threadIdx.x; i < nA + nB; i += blockDim.x) {
        int off;
        if (i < nA) {
            int which = i / Z_W;
            int row = (which == 0) ? 0 : (which == 1 ? 512 : 513);
            off = row*Z_W + (i % Z_W);
        } else {
            int j = i - nA;
            int row = 1 + j/9;
            int c9 = j % 9;
            int col = (c9 < 4) ? c9 : (511 + c9);
            off = row*Z_W + col;
        }
        pl[off] = 0.f;
    }
}

__global__ void jacobi_k(const float* __restrict__ f, const float* __restrict__ coef,
                         const float* __restrict__ xin, float* __restrict__ xout, float w)
{
    int idx = blockIdx.x*blockDim.x + threadIdx.x;
    if (idx >= BNN) return;
    int x = idx % NN_;
    int y = (idx / NN_) % NN_;
    int b = idx / NNN;
    float Ax = 0.f;
    if (y >= 1 && y < NN_-1 && x >= 1 && x < NN_-1)
        Ax = applyA(xin + b*NNN, coef + b*MMM, y, x);
    xout[idx] = xin[idx] + w*(f[idx] - Ax);
}

// residual interior -> padded 512x512 per batch
__global__ void resid_k(const float* __restrict__ f, const float* __restrict__ coef,
                        const float* __restrict__ xin)
{
    int idx = blockIdx.x*blockDim.x + threadIdx.x;
    if (idx >= BMM) return;
    int i = idx % MM;
    int j = (idx / MM) % MM;
    int b = idx / MMM;
    int y = j+1, x = i+1;
    d_r1[b*GDD + j*GD + i] = f[b*NNN + y*NN_ + x] - applyA(xin + b*NNN, coef + b*MMM, y, x);
}

// ---------------------------------------------------------------------------
// 512^3 SGEMM, 128x128x8 tile, 8x8 microtile, packed fma.rn.f32x2
// ---------------------------------------------------------------------------
__global__ __launch_bounds__(256, 2) void gemm512_k(
    const float* __restrict__ A, long long sA, int lda,
    const float* __restrict__ B, long long sB, int ldb,
    float* __restrict__ C, long long sC, int ldc,
    float alpha)
{
    const float* Ab = A + blockIdx.z*sA;
    const float* Bb = B + blockIdx.z*sB;
    float*       Cb = C + blockIdx.z*sC;
    __shared__ float As[8][132];
    __shared__ float Bs[8][128];
    int tid = threadIdx.x;
    int arow = tid >> 1;
    int acol = (tid & 1) << 2;
    int brow = tid >> 5;
    int bcol = (tid & 31) << 2;
    const int m0 = blockIdx.y * 128;
    const int n0 = blockIdx.x * 128;
    int row = (tid >> 4) << 3;
    int col = (tid & 15) << 3;

    unsigned long long acc[8][4];
    #pragma unroll
    for (int i = 0; i < 8; i++)
        #pragma unroll
        for (int j = 0; j < 4; j++) acc[i][j] = 0ull;

    const float* Aptr = Ab + (size_t)(m0+arow)*lda + acol;
    const float* Bptr = Bb + (size_t)brow*ldb + n0 + bcol;

    float4 av4 = *(const float4*)(Aptr);
    float4 bv4 = *(const float4*)(Bptr);

    for (int k0 = 0; k0 < 512; k0 += 8) {
        As[acol+0][arow] = av4.x;
        As[acol+1][arow] = av4.y;
        As[acol+2][arow] = av4.z;
        As[acol+3][arow] = av4.w;
        *(float4*)&Bs[brow][bcol] = bv4;
        __syncthreads();
        if (k0 + 8 < 512) {
            av4 = *(const float4*)(Aptr + (k0 + 8));
            bv4 = *(const float4*)(Bptr + (size_t)(k0 + 8)*ldb);
        }
        #pragma unroll
        for (int k = 0; k < 8; k++) {
            float a_[8];
            #pragma unroll
            for (int i = 0; i < 4; i++) {
                float2 t = *(const float2*)&As[k][row + 2*i];
                a_[2*i] = t.x; a_[2*i+1] = t.y;
            }
            unsigned long long b2[4];
            #pragma unroll
            for (int j = 0; j < 4; j++)
                b2[j] = *(const unsigned long long*)&Bs[k][col + 2*j];
            #pragma unroll
            for (int i = 0; i < 8; i++) {
                unsigned long long a2;
                asm("mov.b64 %0, {%1, %1};" : "=l"(a2) : "f"(a_[i]));
                #pragma unroll
                for (int j = 0; j < 4; j++)
                    asm("fma.rn.f32x2 %0, %1, %2, %0;"
                        : "+l"(acc[i][j]) : "l"(a2), "l"(b2[j]));
            }
        }
        __syncthreads();
    }
    #pragma unroll
    for (int i = 0; i < 8; i++) {
        float* crow = Cb + (size_t)(m0+row+i)*ldc + n0 + col;
        #pragma unroll
        for (int j = 0; j < 4; j++) {
            float lo, hi;
            asm("mov.b64 {%0, %1}, %2;" : "=f"(lo), "=f"(hi) : "l"(acc[i][j]));
            float2 o; o.x = alpha*lo; o.y = alpha*hi;
            *(float2*)&crow[2*j] = o;
        }
    }
}

// ---------------------------------------------------------------------------
// Dual-B GEMM: C = P@B1 + Q@B2  (P,Q per-z; B1,B2 shared). Same tiling.
// ---------------------------------------------------------------------------
__global__ __launch_bounds__(256, 2) void gemm_dualR_k(
    const float* __restrict__ P, const float* __restrict__ Q, long long sPQ, int ldpq,
    const float* __restrict__ B1, const float* __restrict__ B2, int ldb,
    float* __restrict__ C, long long sC, int ldc)
{
    const float* Pb = P + blockIdx.z*sPQ;
    const float* Qb = Q + blockIdx.z*sPQ;
    float*       Cb = C + blockIdx.z*sC;
    __shared__ float Ps[8][132];
    __shared__ float Qs[8][132];
    __shared__ float B1s[8][128];
    __shared__ float B2s[8][128];
    int tid = threadIdx.x;
    int arow = tid >> 1;
    int acol = (tid & 1) << 2;
    int brow = tid >> 5;
    int bcol = (tid & 31) << 2;
    const int m0 = blockIdx.y * 128;
    const int n0 = blockIdx.x * 128;
    int row = (tid >> 4) << 3;
    int col = (tid & 15) << 3;

    unsigned long long acc[8][4];
    #pragma unroll
    for (int i = 0; i < 8; i++)
        #pragma unroll
        for (int j = 0; j < 4; j++) acc[i][j] = 0ull;

    const float* Pptr = Pb + (size_t)(m0+arow)*ldpq + acol;
    const float* Qptr = Qb + (size_t)(m0+arow)*ldpq + acol;
    const float* B1p  = B1 + (size_t)brow*ldb + n0 + bcol;
    const float* B2p  = B2 + (size_t)brow*ldb + n0 + bcol;

    float4 pv = *(const float4*)(Pptr);
    float4 qv = *(const float4*)(Qptr);
    float4 b1v = *(const float4*)(B1p);
    float4 b2v = *(const float4*)(B2p);

    for (int k0 = 0; k0 < 512; k0 += 8) {
        Ps[acol+0][arow] = pv.x; Ps[acol+1][arow] = pv.y;
        Ps[acol+2][arow] = pv.z; Ps[acol+3][arow] = pv.w;
        Qs[acol+0][arow] = qv.x; Qs[acol+1][arow] = qv.y;
        Qs[acol+2][arow] = qv.z; Qs[acol+3][arow] = qv.w;
        *(float4*)&B1s[brow][bcol] = b1v;
        *(float4*)&B2s[brow][bcol] = b2v;
        __syncthreads();
        if (k0 + 8 < 512) {
            pv  = *(const float4*)(Pptr + (k0 + 8));
            qv  = *(const float4*)(Qptr + (k0 + 8));
            b1v = *(const float4*)(B1p + (size_t)(k0 + 8)*ldb);
            b2v = *(const float4*)(B2p + (size_t)(k0 + 8)*ldb);
        }
        #pragma unroll
        for (int k = 0; k < 8; k++) {
            float ap[8], aq[8];
            #pragma unroll
            for (int i = 0; i < 4; i++) {
                float2 t1 = *(const float2*)&Ps[k][row + 2*i];
                float2 t2 = *(const float2*)&Qs[k][row + 2*i];
                ap[2*i] = t1.x; ap[2*i+1] = t1.y;
                aq[2*i] = t2.x; aq[2*i+1] = t2.y;
            }
            unsigned long long c2[4], s2[4];
            #pragma unroll
            for (int j = 0; j < 4; j++) {
                c2[j] = *(const unsigned long long*)&B1s[k][col + 2*j];
                s2[j] = *(const unsigned long long*)&B2s[k][col + 2*j];
            }
            #pragma unroll
            for (int i = 0; i < 8; i++) {
                unsigned long long a2p, a2q;
                asm("mov.b64 %0, {%1, %1};" : "=l"(a2p) : "f"(ap[i]));
                asm("mov.b64 %0, {%1, %1};" : "=l"(a2q) : "f"(aq[i]));
                #pragma unroll
                for (int j = 0; j < 4; j++) {
                    asm("fma.rn.f32x2 %0, %1, %2, %0;"
                        : "+l"(acc[i][j]) : "l"(a2p), "l"(c2[j]));
                    asm("fma.rn.f32x2 %0, %1, %2, %0;"
                        : "+l"(acc[i][j]) : "l"(a2q), "l"(s2[j]));
                }
            }
        }
        __syncthreads();
    }
    #pragma unroll
    for (int i = 0; i < 8; i++) {
        float* crow = Cb + (size_t)(m0+row+i)*ldc + n0 + col;
        #pragma unroll
        for (int j = 0; j < 4; j++) {
            float lo, hi;
            asm("mov.b64 {%0, %1}, %2;" : "=f"(lo), "=f"(hi) : "l"(acc[i][j]));
            float2 o; o.x = lo; o.y = hi;
            *(float2*)&crow[2*j] = o;
        }
    }
}

// ---------------------------------------------------------------------------
// Tiled complex 3x3 conv, both calls merged (grid.z = 16; b = z&7, call = z>>3)
// ---------------------------------------------------------------------------
template<int CIN, int COUT, bool ADJ, bool REALIN, bool THETA>
__global__ __launch_bounds__(256) void conv_k(
    const float* __restrict__ xr, const float* __restrict__ xi,
    long long xbs, long long xcs, int in_bmask,
    const float* __restrict__ wr0, const float* __restrict__ wi0,
    const float* __restrict__ wr1, const float* __restrict__ wi1,
    float* __restrict__ yr, float* __restrict__ yi,
    const float* __restrict__ tr0, const float* __restrict__ ti0,
    const float* __restrict__ tr1, const float* __restrict__ ti1,
    int O0, int I0)
{
    const int NPL = CIN * (REALIN ? 1 : 2);
    __shared__ float sv[CIN*(REALIN?1:2)][34*34];
    __shared__ float swr[COUT*CIN*9];
    __shared__ float swi[COUT*CIN*9];

    int tid = threadIdx.y*32 + threadIdx.x;
    int zc = blockIdx.z;
    int b = zc & 7;
    int call = zc >> 3;
    int by = blockIdx.y, bx = blockIdx.x;

    const float* wr = call ? wr1 : wr0;
    const float* wi = call ? wi1 : wi0;

    for (int t = tid; t < COUT*CIN*9; t += 256) {
        int o = t / (CIN*9);
        int i = (t / 9) % CIN;
        int tap = t % 9;
        int dy = tap / 3, dx = tap % 3;
        int widx;
        float sgn;
        if (!ADJ) { widx = ((b*O0 + o)*I0 + i)*9 + dy*3 + dx; sgn = 1.f; }
        else      { widx = ((b*O0 + i)*I0 + o)*9 + dx*3 + dy; sgn = -1.f; }
        swr[t] = wr[widx];
        swi[t] = sgn * wi[widx];
    }

    int ib = zc & in_bmask;
    for (int p = 0; p < NPL; p++) {
        int ch   = REALIN ? p : (p >> 1);
        bool im  = REALIN ? false : (p & 1);
        const float* src = (im ? xi : xr) + ib*xbs + ch*xcs;
        for (int idx = tid; idx < 34*34; idx += 256) {
            int r = idx / 34, c = idx % 34;
            int gy = by*32 + r - 1;
            int gxo = bx*32 + c + 3;
            sv[p][idx] = src[(size_t)(gy+1)*Z_W + gxo];
        }
    }
    __syncthreads();

    int tx = threadIdx.x;
    int r0 = threadIdx.y * 4;

    float accR[COUT][4];
    float accI[COUT][4];
    #pragma unroll
    for (int o = 0; o < COUT; o++)
        #pragma unroll
        for (int p = 0; p < 4; p++) { accR[o][p] = 0.f; accI[o][p] = 0.f; }

    #pragma unroll
    for (int i = 0; i < CIN; i++) {
        float vr[6][3], vi[6][3];
        #pragma unroll
        for (int ry = 0; ry < 6; ry++)
            #pragma unroll
            for (int cx = 0; cx < 3; cx++) {
                int sidx = (r0+ry)*34 + tx + cx;
                if (REALIN) { vr[ry][cx] = sv[i][sidx]; vi[ry][cx] = 0.f; }
                else        { vr[ry][cx] = sv[2*i][sidx]; vi[ry][cx] = sv[2*i+1][sidx]; }
            }
        #pragma unroll
        for (int o = 0; o < COUT; o++) {
            #pragma unroll
            for (int dy = 0; dy < 3; dy++)
                #pragma unroll
                for (int dx = 0; dx < 3; dx++) {
                    float wrv = swr[(o*CIN + i)*9 + dy*3 + dx];
                    float wiv = swi[(o*CIN + i)*9 + dy*3 + dx];
                    #pragma unroll
                    for (int p = 0; p < 4; p++) {
                        float a = vr[p+dy][dx];
                        float c = vi[p+dy][dx];
                        accR[o][p] += a*wrv - c*wiv;
                        accI[o][p] += a*wiv + c*wrv;
                    }
                }
        }
    }

    int gx = bx*32 + tx;
    if (gx >= PP_) return;
    #pragma unroll
    for (int p = 0; p < 4; p++) {
        int gy = by*32 + r0 + p;
        if (gy >= PP_) continue;
        size_t doff = (size_t)(gy+1)*Z_W + gx + 4;
        #pragma unroll
        for (int o = 0; o < COUT; o++) {
            float ar = accR[o][p], ai = accI[o][p];
            if (THETA) {
                const float* tr = call ? tr1 : tr0;
                const float* ti = call ? ti1 : ti0;
                float trv = tr[(size_t)b*PP_*PP_ + gy*PP_ + gx];
                float tiv = ti[(size_t)b*PP_*PP_ + gy*PP_ + gx];
                float nr = ar*trv - ai*tiv;
                float ni = ar*tiv + ai*trv;
                ar = nr; ai = ni;
            }
            yr[(size_t)(zc*4 + o)*PLANE + doff] = ar;
            yi[(size_t)(zc*4 + o)*PLANE + doff] = ai;
        }
    }
}

// diff for 3M trick: T1 = imag - real (ch0 domain, padded-512 out), z=16
__global__ void diff_k(const float* __restrict__ zr, const float* __restrict__ zi)
{
    int idx = blockIdx.x*blockDim.x + threadIdx.x;
    if (idx >= BG2) return;
    int i = idx % GD;
    int j = (idx / GD) % GD;
    int zc = idx / GDD;
    size_t zo = (size_t)zc*4*PLANE + DOFF + (size_t)j*Z_W + i;
    d_T1[idx] = zi[zo] - zr[zo];
}

// P = m1+m2 ; Q = m1-m2+m3
__global__ void combine_k()
{
    int idx = blockIdx.x*blockDim.x + threadIdx.x;
    if (idx >= BG2) return;
    float a = d_m1[idx], b = d_m2[idx], c = d_m3[idx];
    d_Pm[idx] = a + b;
    d_Qm[idx] = a - b + c;
}

// x[interior] += coef<1 ? R[call0]/coef : R[call1]*coef
__global__ void update_x_k(float* __restrict__ x, const float* __restrict__ coef)
{
    int idx = blockIdx.x*blockDim.x + threadIdx.x;
    if (idx >= BMM) return;
    int i = idx % MM;
    int j = (idx / MM) % MM;
    int b = idx / MMM;
    float c = coef[idx];
    int ro = b*GDD + j*GD + i;
    float e = (c < 1.f) ? d_R[ro]/c : d_R[8*GDD + ro]*c;
    x[b*NNN + (j+1)*NN_ + (i+1)] += e;
}

// ---------------------------------------------------------------------------
// Final norms
// ---------------------------------------------------------------------------
__global__ void norm_partial_k(const float* __restrict__ f, const float* __restrict__ coef,
                               const float* __restrict__ xin, int nblk)
{
    __shared__ double s1[256], s2[256];
    int tid = threadIdx.x;
    double ar = 0.0, af = 0.0;
    for (int idx = blockIdx.x*blockDim.x + tid; idx < BNN; idx += gridDim.x*blockDim.x) {
        int x = idx % NN_;
        int y = (idx / NN_) % NN_;
        int b = idx / NNN;
        float Ax = 0.f;
        if (y >= 1 && y < NN_-1 && x >= 1 && x < NN_-1)
            Ax = applyA(xin + b*NNN, coef + b*MMM, y, x);
        float fv = f[idx];
        float r = fv - Ax;
        ar += (double)r*(double)r;
        af += (double)fv*(double)fv;
    }
    s1[tid] = ar; s2[tid] = af;
    __syncthreads();
    for (int s = 128; s > 0; s >>= 1) {
        if (tid < s) { s1[tid] += s1[tid+s]; s2[tid] += s2[tid+s]; }
        __syncthreads();
    }
    if (tid == 0) { d_part[blockIdx.x] = s1[0]; d_part[nblk + blockIdx.x] = s2[0]; }
}

__global__ void finalize_k(float* __restrict__ out, int nblk)
{
    __shared__ double s1[256], s2[256];
    int tid = threadIdx.x;
    double ar = 0.0, af = 0.0;
    for (int i = tid; i < nblk; i += 256) { ar += d_part[i]; af += d_part[nblk + i]; }
    s1[tid] = ar; s2[tid] = af;
    __syncthreads();
    for (int s = 128; s > 0; s >>= 1) {
        if (tid < s) { s1[tid] += s1[tid+s]; s2[tid] += s2[tid+s]; }
        __syncthreads();
    }
    if (tid == 0) out[0] = (float)sqrt(s1[0] / s2[0]);
}

// ---------------------------------------------------------------------------
// Host launch
// ---------------------------------------------------------------------------
extern "C" void kernel_launch(void* const* d_in, const int* in_sizes, int n_in,
                              void* d_out, int out_size)
{
    const float* f    = (const float*)d_in[0];
    const float* coef = (const float*)d_in[1];
    const float* w11r = (const float*)d_in[2];
    const float* w11i = (const float*)d_in[3];
    const float* w12r = (const float*)d_in[4];
    const float* w12i = (const float*)d_in[5];
    const float* w13r = (const float*)d_in[6];
    const float* w13i = (const float*)d_in[7];
    const float* t1r  = (const float*)d_in[8];
    const float* t1i  = (const float*)d_in[9];
    const float* w21r = (const float*)d_in[10];
    const float* w21i = (const float*)d_in[11];
    const float* w22r = (const float*)d_in[12];
    const float* w22i = (const float*)d_in[13];
    const float* w23r = (const float*)d_in[14];
    const float* w23i = (const float*)d_in[15];
    const float* t2r  = (const float*)d_in[16];
    const float* t2i  = (const float*)d_in[17];
    float* out = (float*)d_out;
    (void)in_sizes; (void)n_in; (void)out_size;

    float *p_x0, *p_x1, *p_r1, *p_T1, *p_rh;
    float *p_Sf, *p_SfT, *p_Cm, *p_Sm, *p_CpS, *p_CmT, *p_SmT;
    float *p_zar, *p_zai, *p_zbr, *p_zbi;
    float *p_m1, *p_m2, *p_m3, *p_P, *p_Q, *p_R;
    cudaGetSymbolAddress((void**)&p_x0,  d_x0);
    cudaGetSymbolAddress((void**)&p_x1,  d_x1);
    cudaGetSymbolAddress((void**)&p_r1,  d_r1);
    cudaGetSymbolAddress((void**)&p_T1,  d_T1);
    cudaGetSymbolAddress((void**)&p_rh,  d_rh);
    cudaGetSymbolAddress((void**)&p_Sf,  d_Sf);
    cudaGetSymbolAddress((void**)&p_SfT, d_SfT);
    cudaGetSymbolAddress((void**)&p_Cm,  d_Cm);
    cudaGetSymbolAddress((void**)&p_Sm,  d_Sm);
    cudaGetSymbolAddress((void**)&p_CpS, d_CpS);
    cudaGetSymbolAddress((void**)&p_CmT, d_CmT);
    cudaGetSymbolAddress((void**)&p_SmT, d_SmT);
    cudaGetSymbolAddress((void**)&p_zar, d_zar);
    cudaGetSymbolAddress((void**)&p_zai, d_zai);
    cudaGetSymbolAddress((void**)&p_zbr, d_zbr);
    cudaGetSymbolAddress((void**)&p_zbi, d_zbi);
    cudaGetSymbolAddress((void**)&p_m1,  d_m1);
    cudaGetSymbolAddress((void**)&p_m2,  d_m2);
    cudaGetSymbolAddress((void**)&p_m3,  d_m3);
    cudaGetSymbolAddress((void**)&p_P,   d_Pm);
    cudaGetSymbolAddress((void**)&p_Q,   d_Qm);
    cudaGetSymbolAddress((void**)&p_R,   d_R);

    // init
    {
        dim3 b2(16,16), g2((GD+15)/16, (GD+15)/16);
        trig_init_k<<<g2, b2>>>();
    }
    fill0_k<<<(BGDD+255)/256, 256>>>(p_r1, BGDD);
    border_k<<<BB, 256>>>(p_rh);
    border_k<<<64, 256>>>(p_zar);
    border_k<<<64, 256>>>(p_zai);
    border_k<<<64, 256>>>(p_zbr);
    border_k<<<64, 256>>>(p_zbi);

    // 10 Jacobi updates from x=0  (epoch==1 -> K=1); first is x = w*f
    const float wrelax = 40.0f / 512.0f;
    first_k<<<(BNN+255)/256, 256>>>(f, p_x0, wrelax);
    float* xa = p_x0;
    float* xb = p_x1;
    for (int t = 0; t < 9; t++) {
        jacobi_k<<<(BNN+255)/256, 256>>>(f, coef, xa, xb, wrelax);
        float* tmp = xa; xa = xb; xb = tmp;
    }
    resid_k<<<(BMM+255)/256, 256>>>(f, coef, xa);

    dim3 gg8(4,4,BB), gg16(4,4,16);
    // shared forward DST: rh = -(1/511^2) * Sf @ r1 @ SfT
    gemm512_k<<<gg8, 256>>>(p_Sf, 0, GD,  p_r1, GDD, GD,  p_T1, GDD, GD, 1.0f);
    gemm512_k<<<gg8, 256>>>(p_T1, GDD, GD, p_SfT, 0, GD,
                            p_rh + DOFF, (long long)PLANE, Z_W,
                            -1.0f/(511.0f*511.0f));

    // both conv chains, merged over z=16
    dim3 cg(16,16,16), cbk(32,8);
    long long cb_bs = 4LL*PLANE, cb_cs = PLANE;

    conv_k<1,4,false,true ,false><<<cg,cbk>>>(p_rh, nullptr, (long long)PLANE, 0, 7,
        w11r, w11i, w21r, w21i, p_zbr, p_zbi, nullptr,nullptr,nullptr,nullptr, 4, 1);
    conv_k<4,4,false,false,false><<<cg,cbk>>>(p_zbr, p_zbi, cb_bs, cb_cs, 15,
        w12r, w12i, w22r, w22i, p_zar, p_zai, nullptr,nullptr,nullptr,nullptr, 4, 4);
    conv_k<4,1,false,false,true ><<<cg,cbk>>>(p_zar, p_zai, cb_bs, cb_cs, 15,
        w13r, w13i, w23r, w23i, p_zbr, p_zbi, t1r, t1i, t2r, t2i, 1, 4);
    conv_k<1,4,true ,false,false><<<cg,cbk>>>(p_zbr, p_zbi, cb_bs, cb_cs, 15,
        w13r, w13i, w23r, w23i, p_zar, p_zai, nullptr,nullptr,nullptr,nullptr, 1, 4);
    conv_k<4,4,true ,false,false><<<cg,cbk>>>(p_zar, p_zai, cb_bs, cb_cs, 15,
        w12r, w12i, w22r, w22i, p_zbr, p_zbi, nullptr,nullptr,nullptr,nullptr, 4, 4);
    conv_k<4,1,true ,false,false><<<cg,cbk>>>(p_zbr, p_zbi, cb_bs, cb_cs, 15,
        w11r, w11i, w21r, w21i, p_zar, p_zai, nullptr,nullptr,nullptr,nullptr, 4, 1);

    // inverse via 3M, both calls at once (z=16)
    diff_k<<<(BG2+255)/256, 256>>>(p_zar, p_zai);
    gemm512_k<<<gg16,256>>>(p_Cm , 0, GD, p_zar + DOFF, 4LL*PLANE, Z_W, p_m1, GDD, GD, 1.0f);
    gemm512_k<<<gg16,256>>>(p_Sm , 0, GD, p_zai + DOFF, 4LL*PLANE, Z_W, p_m2, GDD, GD, 1.0f);
    gemm512_k<<<gg16,256>>>(p_CpS, 0, GD, p_T1, GDD, GD,                p_m3, GDD, GD, 1.0f);
    combine_k<<<(BG2+255)/256, 256>>>();
    gemm_dualR_k<<<gg16,256>>>(p_P, p_Q, GDD, GD, p_CmT, p_SmT, GD, p_R, GDD, GD);

    update_x_k<<<(BMM+255)/256, 256>>>(xa, coef);
    const int nblk = 1024;
    norm_partial_k<<<nblk, 256>>>(f, coef, xa, nblk);
    finalize_k<<<1, 256>>>(out, nblk);
}

// round 5
// speedup vs baseline: 1.4737x; 1.0303x over previous
#include <cuda_runtime.h>
#include <math.h>

// ---------------------------------------------------------------------------
// Problem constants
// ---------------------------------------------------------------------------
#define BB   8
#define NN_  512
#define MM   510
#define PP_  511
#define PI_F 3.14159265358979323846f

#define NNN   (NN_*NN_)
#define BNN   (BB*NNN)
#define MMM   (MM*MM)
#define BMM   (BB*MMM)

// padded GEMM dimension
#define GD    512
#define GDD   (GD*GD)
#define BGDD  (BB*GDD)
#define BG2   (2*BGDD)          // both calls

// conv buffer layout: halo'd planes, stride 520, 514 rows, domain at (+1,+4)
#define Z_W   520
#define Z_H   514
#define PLANE (Z_H*Z_W)
#define DOFF  (Z_W + 4)

// ---------------------------------------------------------------------------
// Static device scratch
// ---------------------------------------------------------------------------
__device__ float  d_x0[BNN];
__device__ float  d_x1[BNN];
__device__ float4 d_st4[BMM];         // (sw, se, sn, ss); sc = -(sum)
__device__ float d_Sf [GDD];
__device__ float d_SfT[GDD];
__device__ float d_Cm [GDD];
__device__ float d_Sm [GDD];
__device__ float d_CpS[GDD];
__device__ float d_CmT[GDD];
__device__ float d_SmT[GDD];
__device__ float d_r1[BGDD];
__device__ float d_T1[BG2];           // forward stage-1 temp (first 8) / diff (16)
__device__ float d_rh[BB*PLANE];      // shared DST result (real)
__device__ float d_zar[16*4*PLANE];   // 16 = batch(8) x call(2)
__device__ float d_zai[16*4*PLANE];
__device__ float d_zbr[16*4*PLANE];
__device__ float d_zbi[16*4*PLANE];
__device__ float d_m1[BG2];
__device__ float d_m2[BG2];
__device__ float d_m3[BG2];
__device__ float d_Pm[BG2];
__device__ float d_Qm[BG2];
__device__ float d_R[BG2];            // call 0 -> slots 0..7, call 1 -> 8..15
__device__ double d_part[2*1024];

// ---------------------------------------------------------------------------
// Trig matrices, padded to 512x512 with zeros
// ---------------------------------------------------------------------------
__global__ void trig_init_k()
{
    int x = blockIdx.x*blockDim.x + threadIdx.x;
    int y = blockIdx.y*blockDim.y + threadIdx.y;
    if (x >= GD || y >= GD) return;
    float sf = 0.f;
    if (y < PP_ && x < MM) {
        int t = (x+1) * (y-255);
        int m = t % 1022; if (m < 0) m += 1022;
        sf = sinf((float)m * (PI_F/511.0f));
    }
    d_Sf [y*GD + x] = sf;
    d_SfT[x*GD + y] = sf;
    float c = 0.f, s = 0.f;
    if (y < MM && x < PP_) {
        int t = y * (x - 255);
        int m = t % 1022; if (m < 0) m += 1022;
        float ang = (float)m * (PI_F/511.0f);
        c = cosf(ang); s = sinf(ang);
    }
    d_Cm [y*GD + x] = c;
    d_Sm [y*GD + x] = s;
    d_CpS[y*GD + x] = c + s;
    d_CmT[x*GD + y] = c;
    d_SmT[x*GD + y] = s;
}

// ---------------------------------------------------------------------------
// Stencil coefficients (precomputed, float4)
// ---------------------------------------------------------------------------
__global__ void stencil_k(const float* __restrict__ coef)
{
    int idx = blockIdx.x*blockDim.x + threadIdx.x;
    if (idx >= BMM) return;
    int i = idx % MM;
    int j = (idx / MM) % MM;
    int b = idx / MMM;
    const float* cb = coef + b*MMM;
    float a   = cb[j*MM + i];
    float aw  = cb[j*MM + (i>0    ? i-1 : 0   )];
    float ae  = cb[j*MM + (i<MM-1 ? i+1 : MM-1)];
    float an  = cb[(j<MM-1 ? j+1 : MM-1)*MM + i];
    float as_ = cb[(j>0    ? j-1 : 0   )*MM + i];
    float4 s;
    s.x = -2.f*aw *a/(aw +a);   // sw
    s.y = -2.f*ae *a/(ae +a);   // se
    s.z = -2.f*an *a/(an +a);   // sn
    s.w = -2.f*as_*a/(as_+a);   // ss
    d_st4[idx] = s;
}

// A(x) at interior point (y,x) in [1,511)
__device__ __forceinline__ float applyA(const float* __restrict__ xb, int b, int y, int x)
{
    int sidx = b*MMM + (y-1)*MM + (x-1);
    float4 s = d_st4[sidx];
    float sc = -(s.x + s.y + s.z + s.w);
    return s.w*xb[(y-1)*NN_+x] + s.x*xb[y*NN_+x-1] + sc*xb[y*NN_+x]
         + s.y*xb[y*NN_+x+1]   + s.z*xb[(y+1)*NN_+x];
}

__global__ void fill0_k(float* __restrict__ p, int n)
{
    int idx = blockIdx.x*blockDim.x + threadIdx.x;
    if (idx < n) p[idx] = 0.f;
}

// first Jacobi sweep from x=0: x = w*f
__global__ void first_k(const float* __restrict__ f, float* __restrict__ xout, float w)
{
    int idx = blockIdx.x*blockDim.x + threadIdx.x;
    if (idx < BNN) xout[idx] = w*f[idx];
}

// zero halo cells of all conv-layout planes in one launch
// grid.x = 8 (rh) + 4*64 (zar/zai/zbr/zbi)
__global__ void border_all_k(float* __restrict__ rh,
                             float* __restrict__ zar, float* __restrict__ zai,
                             float* __restrict__ zbr, float* __restrict__ zbi)
{
    int zb = blockIdx.x;
    float* pl;
    if (zb < 8) pl = rh + (size_t)zb * PLANE;
    else {
        int q = zb - 8;
        int buf = q >> 6;
        int p  = q & 63;
        float* base = (buf == 0) ? zar : (buf == 1) ? zai : (buf == 2) ? zbr : zbi;
        pl = base + (size_t)p * PLANE;
    }
    const int nA = 3*Z_W;          // rows 0, 512, 513
    const int nB = 511*9;          // rows 1..511, cols {0..3, 515..519}
    for (int i = threadIdx.x; i < nA + nB; i += blockDim.x) {
        int off;
        if (i < nA) {
            int which = i / Z_W;
            int row = (which == 0) ? 0 : (which == 1 ? 512 : 513);
            off = row*Z_W + (i % Z_W);
        } else {
            int j = i - nA;
            int row = 1 + j/9;
            int c9 = j % 9;
            int col = (c9 < 4) ? c9 : (511 + c9);
            off = row*Z_W + col;
        }
        pl[off] = 0.f;
    }
}

__global__ void jacobi_k(const float* __restrict__ f, const float* __restrict__ xin,
                         float* __restrict__ xout, float w)
{
    int idx = blockIdx.x*blockDim.x + threadIdx.x;
    if (idx >= BNN) return;
    int x = idx % NN_;
    int y = (idx / NN_) % NN_;
    int b = idx / NNN;
    float Ax = 0.f;
    if (y >= 1 && y < NN_-1 && x >= 1 && x < NN_-1)
        Ax = applyA(xin + b*NNN, b, y, x);
    xout[idx] = xin[idx] + w*(f[idx] - Ax);
}

// residual interior -> padded 512x512 per batch
__global__ void resid_k(const float* __restrict__ f, const float* __restrict__ xin)
{
    int idx = blockIdx.x*blockDim.x + threadIdx.x;
    if (idx >= BMM) return;
    int i = idx % MM;
    int j = (idx / MM) % MM;
    int b = idx / MMM;
    int y = j+1, x = i+1;
    d_r1[b*GDD + j*GD + i] = f[b*NNN + y*NN_ + x] - applyA(xin + b*NNN, b, y, x);
}

// ---------------------------------------------------------------------------
// 512^3 SGEMM, 128x128x8 tile, 8x8 microtile, packed fma.rn.f32x2
// ---------------------------------------------------------------------------
__global__ __launch_bounds__(256, 2) void gemm512_k(
    const float* __restrict__ A, long long sA, int lda,
    const float* __restrict__ Bm, long long sB, int ldb,
    float* __restrict__ C, long long sC, int ldc,
    float alpha)
{
    const float* Ab = A  + blockIdx.z*sA;
    const float* Bb = Bm + blockIdx.z*sB;
    float*       Cb = C  + blockIdx.z*sC;
    __shared__ float As[8][132];
    __shared__ float Bs[8][128];
    int tid = threadIdx.x;
    int arow = tid >> 1;
    int acol = (tid & 1) << 2;
    int brow = tid >> 5;
    int bcol = (tid & 31) << 2;
    const int m0 = blockIdx.y * 128;
    const int n0 = blockIdx.x * 128;
    int row = (tid >> 4) << 3;
    int col = (tid & 15) << 3;

    unsigned long long acc[8][4];
    #pragma unroll
    for (int i = 0; i < 8; i++)
        #pragma unroll
        for (int j = 0; j < 4; j++) acc[i][j] = 0ull;

    const float* Aptr = Ab + (size_t)(m0+arow)*lda + acol;
    const float* Bptr = Bb + (size_t)brow*ldb + n0 + bcol;

    float4 av4 = *(const float4*)(Aptr);
    float4 bv4 = *(const float4*)(Bptr);

    for (int k0 = 0; k0 < 512; k0 += 8) {
        As[acol+0][arow] = av4.x;
        As[acol+1][arow] = av4.y;
        As[acol+2][arow] = av4.z;
        As[acol+3][arow] = av4.w;
        *(float4*)&Bs[brow][bcol] = bv4;
        __syncthreads();
        if (k0 + 8 < 512) {
            av4 = *(const float4*)(Aptr + (k0 + 8));
            bv4 = *(const float4*)(Bptr + (size_t)(k0 + 8)*ldb);
        }
        #pragma unroll
        for (int k = 0; k < 8; k++) {
            float a_[8];
            #pragma unroll
            for (int i = 0; i < 4; i++) {
                float2 t = *(const float2*)&As[k][row + 2*i];
                a_[2*i] = t.x; a_[2*i+1] = t.y;
            }
            unsigned long long b2[4];
            #pragma unroll
            for (int j = 0; j < 4; j++)
                b2[j] = *(const unsigned long long*)&Bs[k][col + 2*j];
            #pragma unroll
            for (int i = 0; i < 8; i++) {
                unsigned long long a2;
                asm("mov.b64 %0, {%1, %1};" : "=l"(a2) : "f"(a_[i]));
                #pragma unroll
                for (int j = 0; j < 4; j++)
                    asm("fma.rn.f32x2 %0, %1, %2, %0;"
                        : "+l"(acc[i][j]) : "l"(a2), "l"(b2[j]));
            }
        }
        __syncthreads();
    }
    #pragma unroll
    for (int i = 0; i < 8; i++) {
        float* crow = Cb + (size_t)(m0+row+i)*ldc + n0 + col;
        #pragma unroll
        for (int j = 0; j < 4; j++) {
            float lo, hi;
            asm("mov.b64 {%0, %1}, %2;" : "=f"(lo), "=f"(hi) : "l"(acc[i][j]));
            float2 o; o.x = alpha*lo; o.y = alpha*hi;
            *(float2*)&crow[2*j] = o;
        }
    }
}

// ---------------------------------------------------------------------------
// Dual-B GEMM: C = P@B1 + Q@B2  (P,Q per-z; B1,B2 shared). Same tiling.
// ---------------------------------------------------------------------------
__global__ __launch_bounds__(256, 2) void gemm_dualR_k(
    const float* __restrict__ P, const float* __restrict__ Q, long long sPQ, int ldpq,
    const float* __restrict__ B1, const float* __restrict__ B2, int ldb,
    float* __restrict__ C, long long sC, int ldc)
{
    const float* Pb = P + blockIdx.z*sPQ;
    const float* Qb = Q + blockIdx.z*sPQ;
    float*       Cb = C + blockIdx.z*sC;
    __shared__ float Ps[8][132];
    __shared__ float Qs[8][132];
    __shared__ float B1s[8][128];
    __shared__ float B2s[8][128];
    int tid = threadIdx.x;
    int arow = tid >> 1;
    int acol = (tid & 1) << 2;
    int brow = tid >> 5;
    int bcol = (tid & 31) << 2;
    const int m0 = blockIdx.y * 128;
    const int n0 = blockIdx.x * 128;
    int row = (tid >> 4) << 3;
    int col = (tid & 15) << 3;

    unsigned long long acc[8][4];
    #pragma unroll
    for (int i = 0; i < 8; i++)
        #pragma unroll
        for (int j = 0; j < 4; j++) acc[i][j] = 0ull;

    const float* Pptr = Pb + (size_t)(m0+arow)*ldpq + acol;
    const float* Qptr = Qb + (size_t)(m0+arow)*ldpq + acol;
    const float* B1p  = B1 + (size_t)brow*ldb + n0 + bcol;
    const float* B2p  = B2 + (size_t)brow*ldb + n0 + bcol;

    float4 pv = *(const float4*)(Pptr);
    float4 qv = *(const float4*)(Qptr);
    float4 b1v = *(const float4*)(B1p);
    float4 b2v = *(const float4*)(B2p);

    for (int k0 = 0; k0 < 512; k0 += 8) {
        Ps[acol+0][arow] = pv.x; Ps[acol+1][arow] = pv.y;
        Ps[acol+2][arow] = pv.z; Ps[acol+3][arow] = pv.w;
        Qs[acol+0][arow] = qv.x; Qs[acol+1][arow] = qv.y;
        Qs[acol+2][arow] = qv.z; Qs[acol+3][arow] = qv.w;
        *(float4*)&B1s[brow][bcol] = b1v;
        *(float4*)&B2s[brow][bcol] = b2v;
        __syncthreads();
        if (k0 + 8 < 512) {
            pv  = *(const float4*)(Pptr + (k0 + 8));
            qv  = *(const float4*)(Qptr + (k0 + 8));
            b1v = *(const float4*)(B1p + (size_t)(k0 + 8)*ldb);
            b2v = *(const float4*)(B2p + (size_t)(k0 + 8)*ldb);
        }
        #pragma unroll
        for (int k = 0; k < 8; k++) {
            float ap[8], aq[8];
            #pragma unroll
            for (int i = 0; i < 4; i++) {
                float2 t1 = *(const float2*)&Ps[k][row + 2*i];
                float2 t2 = *(const float2*)&Qs[k][row + 2*i];
                ap[2*i] = t1.x; ap[2*i+1] = t1.y;
                aq[2*i] = t2.x; aq[2*i+1] = t2.y;
            }
            unsigned long long c2[4], s2[4];
            #pragma unroll
            for (int j = 0; j < 4; j++) {
                c2[j] = *(const unsigned long long*)&B1s[k][col + 2*j];
                s2[j] = *(const unsigned long long*)&B2s[k][col + 2*j];
            }
            #pragma unroll
            for (int i = 0; i < 8; i++) {
                unsigned long long a2p, a2q;
                asm("mov.b64 %0, {%1, %1};" : "=l"(a2p) : "f"(ap[i]));
                asm("mov.b64 %0, {%1, %1};" : "=l"(a2q) : "f"(aq[i]));
                #pragma unroll
                for (int j = 0; j < 4; j++) {
                    asm("fma.rn.f32x2 %0, %1, %2, %0;"
                        : "+l"(acc[i][j]) : "l"(a2p), "l"(c2[j]));
                    asm("fma.rn.f32x2 %0, %1, %2, %0;"
                        : "+l"(acc[i][j]) : "l"(a2q), "l"(s2[j]));
                }
            }
        }
        __syncthreads();
    }
    #pragma unroll
    for (int i = 0; i < 8; i++) {
        float* crow = Cb + (size_t)(m0+row+i)*ldc + n0 + col;
        #pragma unroll
        for (int j = 0; j < 4; j++) {
            float lo, hi;
            asm("mov.b64 {%0, %1}, %2;" : "=f"(lo), "=f"(hi) : "l"(acc[i][j]));
            float2 o; o.x = lo; o.y = hi;
            *(float2*)&crow[2*j] = o;
        }
    }
}

// ---------------------------------------------------------------------------
// Tiled complex 3x3 conv with packed {Re,Im} fma.rn.f32x2 accumulation.
// Both calls merged (grid.z = 16; b = z&7, call = z>>3)
// ---------------------------------------------------------------------------
template<int CIN, int COUT, bool ADJ, bool REALIN, bool THETA>
__global__ __launch_bounds__(256) void conv_k(
    const float* __restrict__ xr, const float* __restrict__ xi,
    long long xbs, long long xcs, int in_bmask,
    const float* __restrict__ wr0, const float* __restrict__ wi0,
    const float* __restrict__ wr1, const float* __restrict__ wi1,
    float* __restrict__ yr, float* __restrict__ yi,
    const float* __restrict__ tr0, const float* __restrict__ ti0,
    const float* __restrict__ tr1, const float* __restrict__ ti1,
    int O0, int I0)
{
    const int NPL = CIN * (REALIN ? 1 : 2);
    __shared__ float sv[CIN*(REALIN?1:2)][34*34];
    __shared__ float2 swa[COUT*CIN*9];   // {wr, wi'}
    __shared__ float2 swb[COUT*CIN*9];   // {-wi', wr}

    int tid = threadIdx.y*32 + threadIdx.x;
    int zc = blockIdx.z;
    int b = zc & 7;
    int call = zc >> 3;
    int by = blockIdx.y, bx = blockIdx.x;

    const float* wr = call ? wr1 : wr0;
    const float* wi = call ? wi1 : wi0;

    for (int t = tid; t < COUT*CIN*9; t += 256) {
        int o = t / (CIN*9);
        int i = (t / 9) % CIN;
        int tap = t % 9;
        int dy = tap / 3, dx = tap % 3;
        int widx;
        float sgn;
        if (!ADJ) { widx = ((b*O0 + o)*I0 + i)*9 + dy*3 + dx; sgn = 1.f; }
        else      { widx = ((b*O0 + i)*I0 + o)*9 + dx*3 + dy; sgn = -1.f; }
        float wrv = wr[widx];
        float wiv = sgn * wi[widx];
        swa[t] = make_float2(wrv, wiv);
        swb[t] = make_float2(-wiv, wrv);
    }

    int ib = zc & in_bmask;
    for (int p = 0; p < NPL; p++) {
        int ch   = REALIN ? p : (p >> 1);
        bool im  = REALIN ? false : (p & 1);
        const float* src = (im ? xi : xr) + ib*xbs + ch*xcs;
        for (int idx = tid; idx < 34*34; idx += 256) {
            int r = idx / 34, c = idx % 34;
            int gy = by*32 + r - 1;
            int gxo = bx*32 + c + 3;
            sv[p][idx] = src[(size_t)(gy+1)*Z_W + gxo];
        }
    }
    __syncthreads();

    int tx = threadIdx.x;
    int r0 = threadIdx.y * 4;

    unsigned long long acc2[COUT][4];   // packed {Re, Im}
    #pragma unroll
    for (int o = 0; o < COUT; o++)
        #pragma unroll
        for (int p = 0; p < 4; p++) acc2[o][p] = 0ull;

    #pragma unroll
    for (int i = 0; i < CIN; i++) {
        float vr[6][3], vi[6][3];
        #pragma unroll
        for (int ry = 0; ry < 6; ry++)
            #pragma unroll
            for (int cx = 0; cx < 3; cx++) {
                int sidx = (r0+ry)*34 + tx + cx;
                if (REALIN) { vr[ry][cx] = sv[i][sidx]; vi[ry][cx] = 0.f; }
                else        { vr[ry][cx] = sv[2*i][sidx]; vi[ry][cx] = sv[2*i+1][sidx]; }
            }
        #pragma unroll
        for (int dy = 0; dy < 3; dy++) {
            #pragma unroll
            for (int dx = 0; dx < 3; dx++) {
                unsigned long long wa[COUT], wb[COUT];
                #pragma unroll
                for (int o = 0; o < COUT; o++) {
                    wa[o] = *(const unsigned long long*)&swa[(o*CIN + i)*9 + dy*3 + dx];
                    if (!REALIN)
                        wb[o] = *(const unsigned long long*)&swb[(o*CIN + i)*9 + dy*3 + dx];
                }
                #pragma unroll
                for (int p = 0; p < 4; p++) {
                    unsigned long long a2;
                    asm("mov.b64 %0, {%1, %1};" : "=l"(a2) : "f"(vr[p+dy][dx]));
                    unsigned long long c2 = 0ull;
                    if (!REALIN)
                        asm("mov.b64 %0, {%1, %1};" : "=l"(c2) : "f"(vi[p+dy][dx]));
                    #pragma unroll
                    for (int o = 0; o < COUT; o++) {
                        asm("fma.rn.f32x2 %0, %1, %2, %0;"
                            : "+l"(acc2[o][p]) : "l"(a2), "l"(wa[o]));
                        if (!REALIN)
                            asm("fma.rn.f32x2 %0, %1, %2, %0;"
                                : "+l"(acc2[o][p]) : "l"(c2), "l"(wb[o]));
                    }
                }
            }
        }
    }

    int gx = bx*32 + tx;
    if (gx >= PP_) return;
    #pragma unroll
    for (int p = 0; p < 4; p++) {
        int gy = by*32 + r0 + p;
        if (gy >= PP_) continue;
        size_t doff = (size_t)(gy+1)*Z_W + gx + 4;
        #pragma unroll
        for (int o = 0; o < COUT; o++) {
            float ar, ai;
            asm("mov.b64 {%0, %1}, %2;" : "=f"(ar), "=f"(ai) : "l"(acc2[o][p]));
            if (THETA) {
                const float* tr = call ? tr1 : tr0;
                const float* ti = call ? ti1 : ti0;
                float trv = tr[(size_t)b*PP_*PP_ + gy*PP_ + gx];
                float tiv = ti[(size_t)b*PP_*PP_ + gy*PP_ + gx];
                float nr = ar*trv - ai*tiv;
                float ni = ar*tiv + ai*trv;
                ar = nr; ai = ni;
            }
            yr[(size_t)(zc*4 + o)*PLANE + doff] = ar;
            yi[(size_t)(zc*4 + o)*PLANE + doff] = ai;
        }
    }
}

// diff for 3M trick: T1 = imag - real (ch0 domain, padded-512 out), z=16
__global__ void diff_k(const float* __restrict__ zr, const float* __restrict__ zi)
{
    int idx = blockIdx.x*blockDim.x + threadIdx.x;
    if (idx >= BG2) return;
    int i = idx % GD;
    int j = (idx / GD) % GD;
    int zc = idx / GDD;
    size_t zo = (size_t)zc*4*PLANE + DOFF + (size_t)j*Z_W + i;
    d_T1[idx] = zi[zo] - zr[zo];
}

// P = m1+m2 ; Q = m1-m2+m3
__global__ void combine_k()
{
    int idx = blockIdx.x*blockDim.x + threadIdx.x;
    if (idx >= BG2) return;
    float a = d_m1[idx], b = d_m2[idx], c = d_m3[idx];
    d_Pm[idx] = a + b;
    d_Qm[idx] = a - b + c;
}

// x[interior] += coef<1 ? R[call0]/coef : R[call1]*coef
__global__ void update_x_k(float* __restrict__ x, const float* __restrict__ coef)
{
    int idx = blockIdx.x*blockDim.x + threadIdx.x;
    if (idx >= BMM) return;
    int i = idx % MM;
    int j = (idx / MM) % MM;
    int b = idx / MMM;
    float c = coef[idx];
    int ro = b*GDD + j*GD + i;
    float e = (c < 1.f) ? d_R[ro]/c : d_R[8*GDD + ro]*c;
    x[b*NNN + (j+1)*NN_ + (i+1)] += e;
}

// ---------------------------------------------------------------------------
// Final norms
// ---------------------------------------------------------------------------
__global__ void norm_partial_k(const float* __restrict__ f, const float* __restrict__ xin, int nblk)
{
    __shared__ double s1[256], s2[256];
    int tid = threadIdx.x;
    double ar = 0.0, af = 0.0;
    for (int idx = blockIdx.x*blockDim.x + tid; idx < BNN; idx += gridDim.x*blockDim.x) {
        int x = idx % NN_;
        int y = (idx / NN_) % NN_;
        int b = idx / NNN;
        float Ax = 0.f;
        if (y >= 1 && y < NN_-1 && x >= 1 && x < NN_-1)
            Ax = applyA(xin + b*NNN, b, y, x);
        float fv = f[idx];
        float r = fv - Ax;
        ar += (double)r*(double)r;
        af += (double)fv*(double)fv;
    }
    s1[tid] = ar; s2[tid] = af;
    __syncthreads();
    for (int s = 128; s > 0; s >>= 1) {
        if (tid < s) { s1[tid] += s1[tid+s]; s2[tid] += s2[tid+s]; }
        __syncthreads();
    }
    if (tid == 0) { d_part[blockIdx.x] = s1[0]; d_part[nblk + blockIdx.x] = s2[0]; }
}

__global__ void finalize_k(float* __restrict__ out, int nblk)
{
    __shared__ double s1[256], s2[256];
    int tid = threadIdx.x;
    double ar = 0.0, af = 0.0;
    for (int i = tid; i < nblk; i += 256) { ar += d_part[i]; af += d_part[nblk + i]; }
    s1[tid] = ar; s2[tid] = af;
    __syncthreads();
    for (int s = 128; s > 0; s >>= 1) {
        if (tid < s) { s1[tid] += s1[tid+s]; s2[tid] += s2[tid+s]; }
        __syncthreads();
    }
    if (tid == 0) out[0] = (float)sqrt(s1[0] / s2[0]);
}

// ---------------------------------------------------------------------------
// Host launch
// ---------------------------------------------------------------------------
extern "C" void kernel_launch(void* const* d_in, const int* in_sizes, int n_in,
                              void* d_out, int out_size)
{
    const float* f    = (const float*)d_in[0];
    const float* coef = (const float*)d_in[1];
    const float* w11r = (const float*)d_in[2];
    const float* w11i = (const float*)d_in[3];
    const float* w12r = (const float*)d_in[4];
    const float* w12i = (const float*)d_in[5];
    const float* w13r = (const float*)d_in[6];
    const float* w13i = (const float*)d_in[7];
    const float* t1r  = (const float*)d_in[8];
    const float* t1i  = (const float*)d_in[9];
    const float* w21r = (const float*)d_in[10];
    const float* w21i = (const float*)d_in[11];
    const float* w22r = (const float*)d_in[12];
    const float* w22i = (const float*)d_in[13];
    const float* w23r = (const float*)d_in[14];
    const float* w23i = (const float*)d_in[15];
    const float* t2r  = (const float*)d_in[16];
    const float* t2i  = (const float*)d_in[17];
    float* out = (float*)d_out;
    (void)in_sizes; (void)n_in; (void)out_size;

    float *p_x0, *p_x1, *p_r1, *p_T1, *p_rh;
    float *p_Sf, *p_SfT, *p_Cm, *p_Sm, *p_CpS, *p_CmT, *p_SmT;
    float *p_zar, *p_zai, *p_zbr, *p_zbi;
    float *p_m1, *p_m2, *p_m3, *p_P, *p_Q, *p_R;
    cudaGetSymbolAddress((void**)&p_x0,  d_x0);
    cudaGetSymbolAddress((void**)&p_x1,  d_x1);
    cudaGetSymbolAddress((void**)&p_r1,  d_r1);
    cudaGetSymbolAddress((void**)&p_T1,  d_T1);
    cudaGetSymbolAddress((void**)&p_rh,  d_rh);
    cudaGetSymbolAddress((void**)&p_Sf,  d_Sf);
    cudaGetSymbolAddress((void**)&p_SfT, d_SfT);
    cudaGetSymbolAddress((void**)&p_Cm,  d_Cm);
    cudaGetSymbolAddress((void**)&p_Sm,  d_Sm);
    cudaGetSymbolAddress((void**)&p_CpS, d_CpS);
    cudaGetSymbolAddress((void**)&p_CmT, d_CmT);
    cudaGetSymbolAddress((void**)&p_SmT, d_SmT);
    cudaGetSymbolAddress((void**)&p_zar, d_zar);
    cudaGetSymbolAddress((void**)&p_zai, d_zai);
    cudaGetSymbolAddress((void**)&p_zbr, d_zbr);
    cudaGetSymbolAddress((void**)&p_zbi, d_zbi);
    cudaGetSymbolAddress((void**)&p_m1,  d_m1);
    cudaGetSymbolAddress((void**)&p_m2,  d_m2);
    cudaGetSymbolAddress((void**)&p_m3,  d_m3);
    cudaGetSymbolAddress((void**)&p_P,   d_Pm);
    cudaGetSymbolAddress((void**)&p_Q,   d_Qm);
    cudaGetSymbolAddress((void**)&p_R,   d_R);

    // init
    {
        dim3 b2(16,16), g2((GD+15)/16, (GD+15)/16);
        trig_init_k<<<g2, b2>>>();
    }
    stencil_k<<<(BMM+255)/256, 256>>>(coef);
    fill0_k<<<(BGDD+255)/256, 256>>>(p_r1, BGDD);
    border_all_k<<<8 + 4*64, 256>>>(p_rh, p_zar, p_zai, p_zbr, p_zbi);

    // 10 Jacobi updates from x=0  (epoch==1 -> K=1); first is x = w*f
    const float wrelax = 40.0f / 512.0f;
    first_k<<<(BNN+255)/256, 256>>>(f, p_x0, wrelax);
    float* xa = p_x0;
    float* xb = p_x1;
    for (int t = 0; t < 9; t++) {
        jacobi_k<<<(BNN+255)/256, 256>>>(f, xa, xb, wrelax);
        float* tmp = xa; xa = xb; xb = tmp;
    }
    resid_k<<<(BMM+255)/256, 256>>>(f, xa);

    dim3 gg8(4,4,BB), gg16(4,4,16);
    // shared forward DST: rh = -(1/511^2) * Sf @ r1 @ SfT
    gemm512_k<<<gg8, 256>>>(p_Sf, 0, GD,  p_r1, GDD, GD,  p_T1, GDD, GD, 1.0f);
    gemm512_k<<<gg8, 256>>>(p_T1, GDD, GD, p_SfT, 0, GD,
                            p_rh + DOFF, (long long)PLANE, Z_W,
                            -1.0f/(511.0f*511.0f));

    // both conv chains, merged over z=16
    dim3 cg(16,16,16), cbk(32,8);
    long long cb_bs = 4LL*PLANE, cb_cs = PLANE;

    conv_k<1,4,false,true ,false><<<cg,cbk>>>(p_rh, nullptr, (long long)PLANE, 0, 7,
        w11r, w11i, w21r, w21i, p_zbr, p_zbi, nullptr,nullptr,nullptr,nullptr, 4, 1);
    conv_k<4,4,false,false,false><<<cg,cbk>>>(p_zbr, p_zbi, cb_bs, cb_cs, 15,
        w12r, w12i, w22r, w22i, p_zar, p_zai, nullptr,nullptr,nullptr,nullptr, 4, 4);
    conv_k<4,1,false,false,true ><<<cg,cbk>>>(p_zar, p_zai, cb_bs, cb_cs, 15,
        w13r, w13i, w23r, w23i, p_zbr, p_zbi, t1r, t1i, t2r, t2i, 1, 4);
    conv_k<1,4,true ,false,false><<<cg,cbk>>>(p_zbr, p_zbi, cb_bs, cb_cs, 15,
        w13r, w13i, w23r, w23i, p_zar, p_zai, nullptr,nullptr,nullptr,nullptr, 1, 4);
    conv_k<4,4,true ,false,false><<<cg,cbk>>>(p_zar, p_zai, cb_bs, cb_cs, 15,
        w12r, w12i, w22r, w22i, p_zbr, p_zbi, nullptr,nullptr,nullptr,nullptr, 4, 4);
    conv_k<4,1,true ,false,false><<<cg,cbk>>>(p_zbr, p_zbi, cb_bs, cb_cs, 15,
        w11r, w11i, w21r, w21i, p_zar, p_zai, nullptr,nullptr,nullptr,nullptr, 4, 1);

    // inverse via 3M, both calls at once (z=16)
    diff_k<<<(BG2+255)/256, 256>>>(p_zar, p_zai);
    gemm512_k<<<gg16,256>>>(p_Cm , 0, GD, p_zar + DOFF, 4LL*PLANE, Z_W, p_m1, GDD, GD, 1.0f);
    gemm512_k<<<gg16,256>>>(p_Sm , 0, GD, p_zai + DOFF, 4LL*PLANE, Z_W, p_m2, GDD, GD, 1.0f);
    gemm512_k<<<gg16,256>>>(p_CpS, 0, GD, p_T1, GDD, GD,                p_m3, GDD, GD, 1.0f);
    combine_k<<<(BG2+255)/256, 256>>>();
    gemm_dualR_k<<<gg16,256>>>(p_P, p_Q, GDD, GD, p_CmT, p_SmT, GD, p_R, GDD, GD);

    update_x_k<<<(BMM+255)/256, 256>>>(xa, coef);
    const int nblk = 1024;
    norm_partial_k<<<nblk, 256>>>(f, xa, nblk);
    finalize_k<<<1, 256>>>(out, nblk);
}